// round 12
// baseline (speedup 1.0000x reference)
#include <cuda_runtime.h>
#include <cuda_bf16.h>
#include <math.h>
#include <stdint.h>

// ============================================================
// Static device scratch
// ============================================================
__device__ float g_x[512 * 1024];
__device__ float g_t[1024 * 512];
__device__ float g_qkv[1024 * 1024];
__device__ float g_attn[8 * 1024 * 1024];
__device__ float g_res[512 * 1024];
__device__ uint32_t g_xs[512 * 2500];
__device__ uint32_t g_h[512 * 2500];
__device__ uint32_t g_r[512 * 2500];
__device__ uint32_t g_tmp[512 * 2500];
__device__ uint32_t g_u[512 * 10000];
__device__ uint32_t g_y1[512 * 10000];
__device__ uint32_t g_y2[512 * 10000];
__device__ float g_bn[2048];

#define UL 4194304
#define U_HEAD  ((size_t)0)
#define U_BODY(i) ((size_t)(1 + (i)) * UL)
#define U_BTAIL ((size_t)17 * UL)
#define U_TAIL  ((size_t)18 * UL)
#define U_C1    ((size_t)19 * UL)
#define U_C2    ((size_t)20 * UL)
#define U_UP    ((size_t)21 * UL)
#define U_TOTAL ((size_t)21 * UL + 16777216)
__device__ __nv_bfloat16 g_uhi[U_TOTAL];
__device__ __nv_bfloat16 g_ulo[U_TOTAL];

__device__ uint32_t g_v[16 * 512 * 2560];
__device__ float g_m[16 * 512 * 2560];

__device__ __nv_bfloat16 g_aqh[8 * 1536 * 512];
__device__ __nv_bfloat16 g_aql[8 * 1536 * 512];
__device__ __nv_bfloat16 g_aph[8 * 512 * 512];
__device__ __nv_bfloat16 g_apl[8 * 512 * 512];

// ============================================================
// Helpers
// ============================================================
__device__ __forceinline__ uint32_t smem_u32(const void* p) {
    uint32_t a;
    asm("{ .reg .u64 t; cvta.to.shared.u64 t, %1; cvt.u32.u64 %0, t; }"
        : "=r"(a) : "l"(p));
    return a;
}

__device__ __forceinline__ void cpasync16(uint32_t dst, const void* src) {
    asm volatile("cp.async.ca.shared.global [%0], [%1], 16;" :: "r"(dst), "l"(src));
}
#define CP_COMMIT asm volatile("cp.async.commit_group;" ::: "memory")
#define CP_WAIT0  asm volatile("cp.async.wait_group 0;" ::: "memory")

__device__ __forceinline__ void ldsm4(uint32_t addr, uint32_t* r) {
    asm volatile("ldmatrix.sync.aligned.m8n8.x4.shared.b16 {%0,%1,%2,%3}, [%4];"
                 : "=r"(r[0]), "=r"(r[1]), "=r"(r[2]), "=r"(r[3]) : "r"(addr));
}

__device__ __forceinline__ void mma16816(float* d, const uint32_t* a,
                                         uint32_t b0, uint32_t b1) {
    asm volatile(
        "mma.sync.aligned.m16n8k16.row.col.f32.bf16.bf16.f32 "
        "{%0,%1,%2,%3}, {%4,%5,%6,%7}, {%8,%9}, {%0,%1,%2,%3};"
        : "+f"(d[0]), "+f"(d[1]), "+f"(d[2]), "+f"(d[3])
        : "r"(a[0]), "r"(a[1]), "r"(a[2]), "r"(a[3]), "r"(b0), "r"(b1));
}

__device__ __forceinline__ void split2(float v0, float v1, uint32_t& hp, uint32_t& lp) {
    __nv_bfloat16 h0 = __float2bfloat16(v0), h1 = __float2bfloat16(v1);
    __nv_bfloat16 l0 = __float2bfloat16(v0 - __bfloat162float(h0));
    __nv_bfloat16 l1 = __float2bfloat16(v1 - __bfloat162float(h1));
    hp = (uint32_t)__bfloat16_as_ushort(h0) | ((uint32_t)__bfloat16_as_ushort(h1) << 16);
    lp = (uint32_t)__bfloat16_as_ushort(l0) | ((uint32_t)__bfloat16_as_ushort(l1) << 16);
}

__device__ __forceinline__ uint32_t packbf(float v) {
    __nv_bfloat16 h = __float2bfloat16(v);
    __nv_bfloat16 l = __float2bfloat16(v - __bfloat162float(h));
    return (uint32_t)__bfloat16_as_ushort(h) | ((uint32_t)__bfloat16_as_ushort(l) << 16);
}

__device__ __forceinline__ float unpackbf(uint32_t p) {
    return __bfloat162float(__ushort_as_bfloat16((unsigned short)(p & 0xffff))) +
           __bfloat162float(__ushort_as_bfloat16((unsigned short)(p >> 16)));
}

// ============================================================
// Weight prep
// ============================================================
__global__ void k_wwino(const float* __restrict__ w, __nv_bfloat16* __restrict__ uhi,
                        __nv_bfloat16* __restrict__ ulo, int Cout, int Cin) {
    int idx = blockIdx.x * 256 + threadIdx.x;
    if (idx >= Cout * Cin) return;
    int co = idx / Cin, ci = idx - co * Cin;
    const float* gp = w + (size_t)idx * 9;
    float g0 = gp[0], g1 = gp[1], g2 = gp[2];
    float g3 = gp[3], g4 = gp[4], g5 = gp[5];
    float g6 = gp[6], g7 = gp[7], g8 = gp[8];
    float t[4][3];
    t[0][0] = g0; t[0][1] = g1; t[0][2] = g2;
    t[1][0] = 0.5f * (g0 + g3 + g6); t[1][1] = 0.5f * (g1 + g4 + g7); t[1][2] = 0.5f * (g2 + g5 + g8);
    t[2][0] = 0.5f * (g0 - g3 + g6); t[2][1] = 0.5f * (g1 - g4 + g7); t[2][2] = 0.5f * (g2 - g5 + g8);
    t[3][0] = g6; t[3][1] = g7; t[3][2] = g8;
#pragma unroll
    for (int i = 0; i < 4; i++) {
        float a0 = t[i][0], a1 = t[i][1], a2 = t[i][2];
        float u[4];
        u[0] = a0;
        u[1] = 0.5f * (a0 + a1 + a2);
        u[2] = 0.5f * (a0 - a1 + a2);
        u[3] = a2;
#pragma unroll
        for (int j = 0; j < 4; j++) {
            int p = i * 4 + j;
            size_t o = (size_t)p * Cout * Cin + (size_t)co * Cin + ci;
            float v = u[j];
            __nv_bfloat16 h = __float2bfloat16(v);
            uhi[o] = h;
            ulo[o] = __float2bfloat16(v - __bfloat162float(h));
        }
    }
}

__global__ void k_wtq(const float* __restrict__ src, __nv_bfloat16* __restrict__ hi,
                      __nv_bfloat16* __restrict__ lo) {
    int idx = blockIdx.x * 256 + threadIdx.x;
    if (idx >= 8 * 1536 * 512) return;
    int blk = idx / (1536 * 512), r = idx - blk * (1536 * 512);
    int f = r >> 9, c = r & 511;
    float v = src[(size_t)blk * 512 * 1536 + c * 1536 + f];
    __nv_bfloat16 h = __float2bfloat16(v);
    hi[idx] = h;
    lo[idx] = __float2bfloat16(v - __bfloat162float(h));
}

__global__ void k_wtp(const float* __restrict__ src, __nv_bfloat16* __restrict__ hi,
                      __nv_bfloat16* __restrict__ lo) {
    int idx = blockIdx.x * 256 + threadIdx.x;
    if (idx >= 8 * 512 * 512) return;
    int blk = idx / (512 * 512), r = idx - blk * (512 * 512);
    int f = r >> 9, c = r & 511;
    float v = src[(size_t)blk * 512 * 512 + c * 512 + f];
    __nv_bfloat16 h = __float2bfloat16(v);
    hi[idx] = h;
    lo[idx] = __float2bfloat16(v - __bfloat162float(h));
}

// ============================================================
// Winograd input transform
// ============================================================
__global__ void k_wino_in(const uint32_t* __restrict__ in, uint32_t* __restrict__ V,
                          int H, int T, int NTpad) {
    int idx = blockIdx.x * 256 + threadIdx.x;
    if (idx >= 512 * NTpad) return;
    int c = idx / NTpad, t = idx - c * NTpad;
    size_t pstride = (size_t)512 * NTpad;
    if (t >= T * T) {
#pragma unroll
        for (int p = 0; p < 16; p++) V[(size_t)p * pstride + idx] = 0;
        return;
    }
    int ty = t / T, tx = t - ty * T;
    int r0 = 2 * ty - 1, c0 = 2 * tx - 1;
    const uint32_t* ip = in + (size_t)c * H * H;
    float d[4][4];
#pragma unroll
    for (int i = 0; i < 4; i++) {
        int rr = r0 + i;
        bool rv = (unsigned)rr < (unsigned)H;
#pragma unroll
        for (int j = 0; j < 4; j++) {
            int cc = c0 + j;
            d[i][j] = (rv && (unsigned)cc < (unsigned)H) ? unpackbf(ip[rr * H + cc]) : 0.f;
        }
    }
    float e[4][4];
#pragma unroll
    for (int j = 0; j < 4; j++) {
        e[0][j] = d[0][j] - d[2][j];
        e[1][j] = d[1][j] + d[2][j];
        e[2][j] = d[2][j] - d[1][j];
        e[3][j] = d[1][j] - d[3][j];
    }
#pragma unroll
    for (int i = 0; i < 4; i++) {
        float f0 = e[i][0] - e[i][2];
        float f1 = e[i][1] + e[i][2];
        float f2 = e[i][2] - e[i][1];
        float f3 = e[i][1] - e[i][3];
        V[(size_t)(i * 4 + 0) * pstride + idx] = packbf(f0);
        V[(size_t)(i * 4 + 1) * pstride + idx] = packbf(f1);
        V[(size_t)(i * 4 + 2) * pstride + idx] = packbf(f2);
        V[(size_t)(i * 4 + 3) * pstride + idx] = packbf(f3);
    }
}

// ============================================================
// agemm smem layout (unchanged)
// ============================================================
#define PITCH 80
#define OFF_ALO (128 * PITCH)
#define OFF_BHI (2 * 128 * PITCH)
#define OFF_BLO (OFF_BHI + 64 * PITCH)
#define STAGE   (OFF_BLO + 64 * PITCH)   // 30720
#define SMEM_DYN (2 * STAGE)             // 61440

// wgemm smem layout: M=256 tile
#define W_ALO  (256 * PITCH)             // 20480
#define W_BHI  (2 * 256 * PITCH)         // 40960
#define W_BLO  (W_BHI + 64 * PITCH)      // 46080
#define W_STAGE (W_BLO + 64 * PITCH)     // 51200
#define W_SMEM  (2 * W_STAGE)            // 102400

// ============================================================
// Winograd batched GEMM, M=256 x N=64 tile, K=512 (16 chunks).
// 8 warps: warp w owns m-rows [w*32, w*32+32) x all 64 px.
// B fragments transient per-gq to cap register pressure.
// ============================================================
__global__ __launch_bounds__(256, 2)
void k_wgemm(const __nv_bfloat16* __restrict__ Ahi, const __nv_bfloat16* __restrict__ Alo,
             const uint32_t* __restrict__ Bp, float* __restrict__ outg,
             long aoz, long boz, long coz, int ldb) {
    extern __shared__ char sm[];
    int tid = threadIdx.x, wid = tid >> 5, lane = tid & 31;
    int n0 = blockIdx.x * 64, m0 = blockIdx.y * 256, z = blockIdx.z;
    uint32_t sb = smem_u32(sm);

    // A: one row per thread, 32 bf16 = 64B hi + 64B lo = 8 cp.async
    const __nv_bfloat16* whp = Ahi + (size_t)z * aoz + (size_t)(m0 + tid) * 512;
    const __nv_bfloat16* wlp = Alo + (size_t)z * aoz + (size_t)(m0 + tid) * 512;
    uint32_t a_off = tid * PITCH;

    int bpix = tid & 63, bkg = tid >> 6;
    const uint32_t* bbase = Bp + (size_t)z * boz + n0 + bpix;
    uint32_t b_off = W_BHI + bpix * PITCH + bkg * 16;

    uint32_t rBp[8];

    auto a_issue = [&](int ch, int buf) {
        int kk = ch << 5;
        uint32_t d0 = sb + a_off + buf * W_STAGE;
        cpasync16(d0, whp + kk);
        cpasync16(d0 + 16, whp + kk + 8);
        cpasync16(d0 + 32, whp + kk + 16);
        cpasync16(d0 + 48, whp + kk + 24);
        cpasync16(d0 + W_ALO, wlp + kk);
        cpasync16(d0 + W_ALO + 16, wlp + kk + 8);
        cpasync16(d0 + W_ALO + 32, wlp + kk + 16);
        cpasync16(d0 + W_ALO + 48, wlp + kk + 24);
        CP_COMMIT;
    };
    auto b_load = [&](int ch) {
        int kk = ch << 5;
#pragma unroll
        for (int j = 0; j < 8; j++)
            rBp[j] = bbase[(size_t)(kk + bkg * 8 + j) * ldb];
    };
    auto b_store = [&](int buf) {
        uint32_t bo = buf * W_STAGE;
#pragma unroll
        for (int j = 0; j < 8; j += 2) {
            uint32_t hp = __byte_perm(rBp[j], rBp[j + 1], 0x5410);
            uint32_t lp = __byte_perm(rBp[j], rBp[j + 1], 0x7632);
            *(uint32_t*)(sm + (b_off - W_BHI) + W_BHI + bo + j * 2) = hp;
            *(uint32_t*)(sm + (b_off - W_BHI) + W_BLO + bo + j * 2) = lp;
        }
    };

    uint32_t a_ld = sb + (wid * 32 + (lane & 15)) * PITCH + (lane >> 4) * 16;
    uint32_t b_ld = sb + W_BHI + ((lane & 15)) * PITCH + (lane >> 4) * 16;

    float acc[2][8][4];
#pragma unroll
    for (int i = 0; i < 2; i++)
#pragma unroll
        for (int j = 0; j < 8; j++)
#pragma unroll
            for (int e = 0; e < 4; e++) acc[i][j][e] = 0.f;

    a_issue(0, 0);
    b_load(0);
    b_store(0);
    CP_WAIT0;
    __syncthreads();

    for (int ch = 0; ch < 16; ch++) {
        if (ch < 15) {
            a_issue(ch + 1, (ch + 1) & 1);
            b_load(ch + 1);
        }
        uint32_t bo = (ch & 1) * W_STAGE;
#pragma unroll
        for (int ks = 0; ks < 2; ks++) {
            uint32_t Ah[2][4], Al[2][4];
#pragma unroll
            for (int mt = 0; mt < 2; mt++) {
                ldsm4(a_ld + bo + mt * (16 * PITCH) + ks * 32, Ah[mt]);
                ldsm4(a_ld + bo + W_ALO + mt * (16 * PITCH) + ks * 32, Al[mt]);
            }
#pragma unroll
            for (int gq = 0; gq < 4; gq++) {
                uint32_t Bh[4], Bl[4];
                ldsm4(b_ld + bo + gq * (16 * PITCH) + ks * 32, Bh);
                ldsm4(b_ld + bo + (W_BLO - W_BHI) + gq * (16 * PITCH) + ks * 32, Bl);
#pragma unroll
                for (int half = 0; half < 2; half++) {
                    int nt = gq * 2 + half;
                    uint32_t bh0 = Bh[half], bh1 = Bh[half + 2];
                    uint32_t bl0 = Bl[half], bl1 = Bl[half + 2];
#pragma unroll
                    for (int mt = 0; mt < 2; mt++) {
                        mma16816(acc[mt][nt], Ah[mt], bh0, bh1);
                        mma16816(acc[mt][nt], Ah[mt], bl0, bl1);
                        mma16816(acc[mt][nt], Al[mt], bh0, bh1);
                    }
                }
            }
        }
        if (ch < 15) {
            b_store((ch + 1) & 1);
            CP_WAIT0;
            __syncthreads();
        }
    }

    float* op = outg + (size_t)z * coz;
#pragma unroll
    for (int mt = 0; mt < 2; mt++) {
#pragma unroll
        for (int half = 0; half < 2; half++) {
            int co = m0 + wid * 32 + mt * 16 + (lane >> 2) + half * 8;
#pragma unroll
            for (int nt = 0; nt < 8; nt++) {
#pragma unroll
                for (int e = 0; e < 2; e++) {
                    int p = n0 + nt * 8 + (lane & 3) * 2 + e;
                    op[(size_t)co * ldb + p] = acc[mt][nt][half * 2 + e];
                }
            }
        }
    }
}

// ============================================================
// Winograd output transform (fused epilogue)
// ============================================================
__global__ void k_wino_out(const float* __restrict__ Mb, uint32_t* __restrict__ out,
                           const float* __restrict__ bias,
                           const float* __restrict__ bnsc, const float* __restrict__ bnsh,
                           const uint32_t* __restrict__ resid,
                           int Cout, int T, int NTpad, int relu, int ps) {
    int idx = blockIdx.x * 256 + threadIdx.x;
    if (idx >= Cout * T * T) return;
    int co = idx / (T * T), t = idx - co * (T * T);
    int ty = t / T, tx = t - ty * T;
    int H = 2 * T, P = H * H;
    size_t pstride = (size_t)Cout * NTpad;
    const float* mp = Mb + (size_t)co * NTpad + t;
    float m[4][4];
#pragma unroll
    for (int i = 0; i < 4; i++)
#pragma unroll
        for (int j = 0; j < 4; j++)
            m[i][j] = mp[(size_t)(i * 4 + j) * pstride];
    float s0[4], s1[4];
#pragma unroll
    for (int j = 0; j < 4; j++) {
        s0[j] = m[0][j] + m[1][j] + m[2][j];
        s1[j] = m[1][j] - m[2][j] - m[3][j];
    }
    float y[2][2];
    y[0][0] = s0[0] + s0[1] + s0[2];
    y[0][1] = s0[1] - s0[2] - s0[3];
    y[1][0] = s1[0] + s1[1] + s1[2];
    y[1][1] = s1[1] - s1[2] - s1[3];

    float bv = bias ? bias[co] : 0.f;
    float sc = bnsc ? bnsc[co] : 1.f;
    float sh = bnsh ? bnsh[co] : 0.f;
#pragma unroll
    for (int i = 0; i < 2; i++) {
#pragma unroll
        for (int j = 0; j < 2; j++) {
            int yy = 2 * ty + i, xx = 2 * tx + j;
            int pix = yy * H + xx;
            float v = y[i][j] + bv;
            if (bnsc) v = v * sc + sh;
            if (resid) v += unpackbf(resid[(size_t)co * P + pix]);
            if (relu) v = fmaxf(v, 0.f);
            uint32_t pk = packbf(v);
            if (ps) {
                int c = co >> 2, ry = (co >> 1) & 1, rx = co & 1;
                out[(size_t)c * (4 * P) + (size_t)(2 * yy + ry) * (2 * H) + 2 * xx + rx] = pk;
            } else {
                out[(size_t)co * P + pix] = pk;
            }
        }
    }
}

// ============================================================
// Attention tensor GEMM (unchanged, proven)
// ============================================================
template <int AM, int TRANS>
__global__ __launch_bounds__(256, 2)
void k_agemm(const __nv_bfloat16* __restrict__ Ahi, const __nv_bfloat16* __restrict__ Alo,
             const float* __restrict__ Af, const float* __restrict__ Bfg,
             float* __restrict__ outg, const float* __restrict__ bias,
             const float* __restrict__ resid,
             long aoz, long boz, long coz,
             int K, int lda, int ldb, int ldo, int Nn, float scale) {
    extern __shared__ char sm[];
    int tid = threadIdx.x, wid = tid >> 5, lane = tid & 31;
    int n0 = blockIdx.x * 64, m0 = blockIdx.y * 128, z = blockIdx.z;
    uint32_t sb = smem_u32(sm);
    int NCH = K >> 5;

    const float* Bf = Bfg + (size_t)z * boz;
    float* outp = outg + (size_t)z * coz;

    int arow = tid >> 1, aseg = tid & 1;
    int krow = tid >> 3, mseg = tid & 7;
    const __nv_bfloat16 *whp = nullptr, *wlp = nullptr;
    const float* afp = nullptr;
    if constexpr (AM == 0) {
        whp = Ahi + (size_t)z * aoz + (size_t)(m0 + arow) * lda + aseg * 16;
        wlp = Alo + (size_t)z * aoz + (size_t)(m0 + arow) * lda + aseg * 16;
    } else if constexpr (AM == 1) {
        afp = Af + (size_t)z * aoz + (size_t)krow * lda + m0 + mseg * 16;
    } else {
        afp = Af + (size_t)z * aoz + (size_t)(m0 + arow) * lda + aseg * 16;
    }
    uint32_t a_off = arow * PITCH + aseg * 32;

    int bpix = tid & 63, bkg = tid >> 6;
    uint32_t b_off = OFF_BHI + bpix * PITCH + bkg * 16;

    uint4 rAh[2], rAl[2];
    float rA[16];
    float rB[8];

    auto load_gmem = [&](int ch) {
        int kk = ch << 5;
        if constexpr (AM == 0) {
            rAh[0] = *(const uint4*)(whp + kk);
            rAh[1] = *(const uint4*)(whp + kk + 8);
            rAl[0] = *(const uint4*)(wlp + kk);
            rAl[1] = *(const uint4*)(wlp + kk + 8);
        } else if constexpr (AM == 1) {
            const float* p = afp + (size_t)kk * lda;
            *(float4*)(rA + 0) = *(const float4*)(p + 0);
            *(float4*)(rA + 4) = *(const float4*)(p + 4);
            *(float4*)(rA + 8) = *(const float4*)(p + 8);
            *(float4*)(rA + 12) = *(const float4*)(p + 12);
        } else {
            const float* p = afp + kk;
            *(float4*)(rA + 0) = *(const float4*)(p + 0);
            *(float4*)(rA + 4) = *(const float4*)(p + 4);
            *(float4*)(rA + 8) = *(const float4*)(p + 8);
            *(float4*)(rA + 12) = *(const float4*)(p + 12);
        }
#pragma unroll
        for (int j = 0; j < 8; j++)
            rB[j] = Bf[(size_t)(kk + bkg * 8 + j) * ldb + n0 + bpix];
    };

    auto store_smem = [&](int buf) {
        uint32_t bo = buf * STAGE;
        if constexpr (AM == 0) {
            *(uint4*)(sm + a_off + bo) = rAh[0];
            *(uint4*)(sm + a_off + bo + 16) = rAh[1];
            *(uint4*)(sm + a_off + bo + OFF_ALO) = rAl[0];
            *(uint4*)(sm + a_off + bo + OFF_ALO + 16) = rAl[1];
        } else if constexpr (AM == 1) {
#pragma unroll
            for (int j = 0; j < 16; j++) {
                float v = rA[j];
                __nv_bfloat16 h = __float2bfloat16(v);
                __nv_bfloat16 l = __float2bfloat16(v - __bfloat162float(h));
                uint32_t off = (mseg * 16 + j) * PITCH + krow * 2;
                *(__nv_bfloat16*)(sm + bo + off) = h;
                *(__nv_bfloat16*)(sm + bo + OFF_ALO + off) = l;
            }
        } else {
            uint32_t hp[8], lp[8];
#pragma unroll
            for (int j = 0; j < 8; j++) split2(rA[2 * j], rA[2 * j + 1], hp[j], lp[j]);
            *(uint4*)(sm + bo + a_off) = *(uint4*)hp;
            *(uint4*)(sm + bo + a_off + 16) = *(uint4*)(hp + 4);
            *(uint4*)(sm + bo + OFF_ALO + a_off) = *(uint4*)lp;
            *(uint4*)(sm + bo + OFF_ALO + a_off + 16) = *(uint4*)(lp + 4);
        }
#pragma unroll
        for (int j = 0; j < 8; j += 2) {
            uint32_t hp, lp;
            split2(rB[j], rB[j + 1], hp, lp);
            *(uint32_t*)(sm + (b_off - OFF_BHI) + OFF_BHI + bo + j * 2) = hp;
            *(uint32_t*)(sm + (b_off - OFF_BHI) + OFF_BLO + bo + j * 2) = lp;
        }
    };

    int warp_m = wid & 3, warp_n = wid >> 2;
    uint32_t a_ld = sb + (warp_m * 32 + (lane & 15)) * PITCH + (lane >> 4) * 16;
    uint32_t b_ld = sb + OFF_BHI + (warp_n * 32 + (lane & 15)) * PITCH + (lane >> 4) * 16;

    float acc[2][4][4];
#pragma unroll
    for (int i = 0; i < 2; i++)
#pragma unroll
        for (int j = 0; j < 4; j++)
#pragma unroll
            for (int e = 0; e < 4; e++) acc[i][j][e] = 0.f;

    load_gmem(0);
    store_smem(0);
    __syncthreads();

    for (int ch = 0; ch < NCH; ch++) {
        if (ch + 1 < NCH) load_gmem(ch + 1);
        uint32_t bo = (ch & 1) * STAGE;
#pragma unroll
        for (int ks = 0; ks < 2; ks++) {
            uint32_t Ah[2][4], Al[2][4], Bh[2][4], Bl[2][4];
#pragma unroll
            for (int mt = 0; mt < 2; mt++) {
                ldsm4(a_ld + bo + mt * (16 * PITCH) + ks * 32, Ah[mt]);
                ldsm4(a_ld + bo + OFF_ALO + mt * (16 * PITCH) + ks * 32, Al[mt]);
            }
#pragma unroll
            for (int gq = 0; gq < 2; gq++) {
                ldsm4(b_ld + bo + gq * (16 * PITCH) + ks * 32, Bh[gq]);
                ldsm4(b_ld + bo + (OFF_BLO - OFF_BHI) + gq * (16 * PITCH) + ks * 32, Bl[gq]);
            }
#pragma unroll
            for (int mt = 0; mt < 2; mt++)
#pragma unroll
                for (int nt = 0; nt < 4; nt++) {
                    int gq = nt >> 1, idx = nt & 1;
                    uint32_t bh0 = Bh[gq][idx], bh1 = Bh[gq][idx + 2];
                    uint32_t bl0 = Bl[gq][idx], bl1 = Bl[gq][idx + 2];
                    mma16816(acc[mt][nt], Ah[mt], bh0, bh1);
                    mma16816(acc[mt][nt], Ah[mt], bl0, bl1);
                    mma16816(acc[mt][nt], Al[mt], bh0, bh1);
                }
        }
        if (ch + 1 < NCH) {
            store_smem((ch + 1) & 1);
            __syncthreads();
        }
    }

#pragma unroll
    for (int mt = 0; mt < 2; mt++) {
#pragma unroll
        for (int half = 0; half < 2; half++) {
            int co = m0 + warp_m * 32 + mt * 16 + (lane >> 2) + half * 8;
            float bv = bias ? bias[co] : 0.f;
#pragma unroll
            for (int nt = 0; nt < 4; nt++) {
#pragma unroll
                for (int e = 0; e < 2; e++) {
                    int p = n0 + warp_n * 32 + nt * 8 + (lane & 3) * 2 + e;
                    if (p >= Nn) continue;
                    float v = acc[mt][nt][half * 2 + e] * scale + bv;
                    if (resid) v += resid[(size_t)co * ldo + p];
                    if (TRANS) outp[(size_t)p * ldo + co] = v;
                    else outp[(size_t)co * ldo + p] = v;
                }
            }
        }
    }
}

// ============================================================
// Softmax
// ============================================================
__global__ __launch_bounds__(256)
void k_softmax() {
    float* p = g_attn + (size_t)blockIdx.x * 1024;
    int tid = threadIdx.x;
    float4 v = *(float4*)(p + tid * 4);
    float mx = fmaxf(fmaxf(v.x, v.y), fmaxf(v.z, v.w));
#pragma unroll
    for (int o = 16; o > 0; o >>= 1) mx = fmaxf(mx, __shfl_xor_sync(0xffffffffu, mx, o));
    __shared__ float smx[8], ssm[8];
    if ((tid & 31) == 0) smx[tid >> 5] = mx;
    __syncthreads();
    mx = smx[0];
#pragma unroll
    for (int i = 1; i < 8; i++) mx = fmaxf(mx, smx[i]);
    float e0 = expf(v.x - mx), e1 = expf(v.y - mx), e2 = expf(v.z - mx), e3 = expf(v.w - mx);
    float s = e0 + e1 + e2 + e3;
#pragma unroll
    for (int o = 16; o > 0; o >>= 1) s += __shfl_xor_sync(0xffffffffu, s, o);
    if ((tid & 31) == 0) ssm[tid >> 5] = s;
    __syncthreads();
    s = ssm[0] + ssm[1] + ssm[2] + ssm[3] + ssm[4] + ssm[5] + ssm[6] + ssm[7];
    float inv = 1.f / s;
    *(float4*)(p + tid * 4) = make_float4(e0 * inv, e1 * inv, e2 * inv, e3 * inv);
}

// ============================================================
// Grid sample, BN fold, c3
// ============================================================
__device__ __forceinline__ int map_idx(int o, int size, bool* valid) {
    float vv = -49.f + 2.f * (float)o;
    float gg = (vv + 51.2f) / 102.4f * 2.f - 1.f;
    float f = ((gg + 1.f) * (float)size - 1.f) * 0.5f;
    int ii = (int)rintf(f);
    *valid = (ii >= 0) && (ii < size);
    return min(max(ii, 0), size - 1);
}

__global__ void k_gridsample() {
    int idx = blockIdx.x * 256 + threadIdx.x;
    if (idx >= 512 * 2500) return;
    int c = idx / 2500, p = idx - c * 2500;
    int oy = p / 50, ox = p - oy * 50;
    bool vy, vx;
    int iy = map_idx(oy, 32, &vy);
    int ix = map_idx(ox, 32, &vx);
    float v = (vy && vx) ? g_x[(size_t)c * 1024 + iy * 32 + ix] : 0.f;
    g_xs[idx] = packbf(v);
}

__global__ void k_bnprep(const float* g1, const float* b1, const float* m1, const float* v1,
                         const float* g2, const float* b2, const float* m2, const float* v2) {
    int c = blockIdx.x * 256 + threadIdx.x;
    if (c >= 512) return;
    float s1 = g1[c] / sqrtf(v1[c] + 1e-5f);
    g_bn[c] = s1;
    g_bn[512 + c] = b1[c] - m1[c] * s1;
    float s2 = g2[c] / sqrtf(v2[c] + 1e-5f);
    g_bn[1024 + c] = s2;
    g_bn[1536 + c] = b2[c] - m2[c] * s2;
}

__global__ void k_c3(const float* __restrict__ w, const float* __restrict__ b,
                     float* __restrict__ out) {
    int idx = blockIdx.x * 256 + threadIdx.x;
    if (idx >= 60000) return;
    int cls = idx / 10000, p = idx - cls * 10000;
    const float* wr = w + cls * 512;
    float s = b[cls];
#pragma unroll 4
    for (int c = 0; c < 512; c++) s += unpackbf(g_y1[(size_t)c * 10000 + p]) * wr[c];
    out[idx] = 1.f / (1.f + expf(-s));
}

// ============================================================
// Host orchestration
// ============================================================
extern "C" void kernel_launch(void* const* d_in, const int* in_sizes, int n_in,
                              void* d_out, int out_size) {
    const float* x       = (const float*)d_in[0];
    const float* qkv_w   = (const float*)d_in[1];
    const float* proj_w  = (const float*)d_in[2];
    const float* proj_b  = (const float*)d_in[3];
    const float* head_w  = (const float*)d_in[4];
    const float* head_b  = (const float*)d_in[5];
    const float* body_w  = (const float*)d_in[6];
    const float* body_b  = (const float*)d_in[7];
    const float* btail_w = (const float*)d_in[8];
    const float* btail_b = (const float*)d_in[9];
    const float* up_w    = (const float*)d_in[10];
    const float* up_b    = (const float*)d_in[11];
    const float* tail_w  = (const float*)d_in[12];
    const float* tail_b  = (const float*)d_in[13];
    const float* c1_w    = (const float*)d_in[14];
    const float* bn1_g   = (const float*)d_in[15];
    const float* bn1_b   = (const float*)d_in[16];
    const float* bn1_m   = (const float*)d_in[17];
    const float* bn1_v   = (const float*)d_in[18];
    const float* c2_w    = (const float*)d_in[19];
    const float* bn2_g   = (const float*)d_in[20];
    const float* bn2_b   = (const float*)d_in[21];
    const float* bn2_m   = (const float*)d_in[22];
    const float* bn2_v   = (const float*)d_in[23];
    const float* c3_w    = (const float*)d_in[24];
    const float* c3_b    = (const float*)d_in[25];
    float* out = (float*)d_out;

    float *p_x, *p_t, *p_qkv, *p_attn, *p_res, *p_bn, *p_m;
    uint32_t *p_xs, *p_h, *p_r, *p_tmp, *p_u, *p_y1, *p_y2, *p_v;
    __nv_bfloat16 *p_uhi, *p_ulo, *p_aqh, *p_aql, *p_aph, *p_apl;
    cudaGetSymbolAddress((void**)&p_x, g_x);
    cudaGetSymbolAddress((void**)&p_t, g_t);
    cudaGetSymbolAddress((void**)&p_qkv, g_qkv);
    cudaGetSymbolAddress((void**)&p_attn, g_attn);
    cudaGetSymbolAddress((void**)&p_res, g_res);
    cudaGetSymbolAddress((void**)&p_xs, g_xs);
    cudaGetSymbolAddress((void**)&p_h, g_h);
    cudaGetSymbolAddress((void**)&p_r, g_r);
    cudaGetSymbolAddress((void**)&p_tmp, g_tmp);
    cudaGetSymbolAddress((void**)&p_u, g_u);
    cudaGetSymbolAddress((void**)&p_y1, g_y1);
    cudaGetSymbolAddress((void**)&p_y2, g_y2);
    cudaGetSymbolAddress((void**)&p_bn, g_bn);
    cudaGetSymbolAddress((void**)&p_v, g_v);
    cudaGetSymbolAddress((void**)&p_m, g_m);
    cudaGetSymbolAddress((void**)&p_uhi, g_uhi);
    cudaGetSymbolAddress((void**)&p_ulo, g_ulo);
    cudaGetSymbolAddress((void**)&p_aqh, g_aqh);
    cudaGetSymbolAddress((void**)&p_aql, g_aql);
    cudaGetSymbolAddress((void**)&p_aph, g_aph);
    cudaGetSymbolAddress((void**)&p_apl, g_apl);

    cudaFuncSetAttribute(k_wgemm, cudaFuncAttributeMaxDynamicSharedMemorySize, W_SMEM);
    cudaFuncSetAttribute(k_agemm<0, 0>, cudaFuncAttributeMaxDynamicSharedMemorySize, SMEM_DYN);
    cudaFuncSetAttribute(k_agemm<0, 1>, cudaFuncAttributeMaxDynamicSharedMemorySize, SMEM_DYN);
    cudaFuncSetAttribute(k_agemm<1, 0>, cudaFuncAttributeMaxDynamicSharedMemorySize, SMEM_DYN);
    cudaFuncSetAttribute(k_agemm<2, 1>, cudaFuncAttributeMaxDynamicSharedMemorySize, SMEM_DYN);

    cudaMemcpyAsync(p_x, x, (size_t)512 * 1024 * sizeof(float),
                    cudaMemcpyDeviceToDevice, 0);

    // ---- weight prep. ncu -s 5 counts the memcpy, so the dummy wgemm
    //      below sits at profiled index 5. ----
    auto wprep1 = [&](const float* w, size_t uoff, int Cout) {
        k_wwino<<<(Cout * 512 + 255) / 256, 256>>>(w, p_uhi + uoff, p_ulo + uoff, Cout, 512);
    };
    wprep1(head_w, U_HEAD, 512);                                        // prof idx 1
    k_wtq<<<(8 * 1536 * 512 + 255) / 256, 256>>>(qkv_w, p_aqh, p_aql);  // 2
    k_wtp<<<(8 * 512 * 512 + 255) / 256, 256>>>(proj_w, p_aph, p_apl);  // 3
    wprep1(body_w + (size_t)0 * 512 * 512 * 9, U_BODY(0), 512);         // 4
    // 5: DIAGNOSTIC dummy wgemm (reads zero-init g_v; g_m overwritten later)
    k_wgemm<<<dim3(10, 2, 16), 256, W_SMEM>>>(p_uhi + U_HEAD, p_ulo + U_HEAD, p_v, p_m,
                                              (long)512 * 512, (long)512 * 640,
                                              (long)512 * 640, 640);
    for (int i = 1; i < 16; i++)
        wprep1(body_w + (size_t)i * 512 * 512 * 9, U_BODY(i), 512);
    wprep1(btail_w, U_BTAIL, 512);
    wprep1(tail_w, U_TAIL, 512);
    wprep1(c1_w, U_C1, 512);
    wprep1(c2_w, U_C2, 512);
    k_wwino<<<(2048 * 512 + 255) / 256, 256>>>(up_w, p_uhi + U_UP, p_ulo + U_UP, 2048, 512);

    const float scale = 0.044194173824159216f;  // 512^-0.5

    // ---- 8 self-attention blocks ----
    for (int i = 0; i < 8; i++) {
        k_agemm<0, 0><<<dim3(16, 8, 1), 256, SMEM_DYN>>>(
            p_aqh + (size_t)i * 1536 * 512, p_aql + (size_t)i * 1536 * 512,
            nullptr, p_x, p_qkv, nullptr, nullptr,
            0, 0, 0, 512, 512, 1024, 1024, 1024, 1.f);
        k_agemm<0, 1><<<dim3(16, 4, 1), 256, SMEM_DYN>>>(
            p_aqh + (size_t)i * 1536 * 512 + (size_t)1024 * 512,
            p_aql + (size_t)i * 1536 * 512 + (size_t)1024 * 512,
            nullptr, p_x, p_t, nullptr, nullptr,
            0, 0, 0, 512, 512, 1024, 512, 1024, 1.f);
        k_agemm<1, 0><<<dim3(16, 8, 8), 256, SMEM_DYN>>>(
            nullptr, nullptr, p_qkv, p_qkv + (size_t)512 * 1024, p_attn,
            nullptr, nullptr,
            64 * 1024, 64 * 1024, 1l << 20, 64, 1024, 1024, 1024, 1024, scale);
        k_softmax<<<8192, 256>>>();
        k_agemm<2, 1><<<dim3(1, 8, 8), 256, SMEM_DYN>>>(
            nullptr, nullptr, p_attn, p_t, p_res, nullptr, nullptr,
            1l << 20, 64, 64 * 1024, 1024, 1024, 512, 1024, 64, 1.f);
        k_agemm<0, 0><<<dim3(16, 4, 1), 256, SMEM_DYN>>>(
            p_aph + (size_t)i * 512 * 512, p_apl + (size_t)i * 512 * 512,
            nullptr, p_res, p_x, proj_b + (size_t)i * 512, p_x,
            0, 0, 0, 512, 512, 1024, 1024, 1024, 1.f);
    }

    // ---- grid transform + BN fold ----
    k_gridsample<<<(512 * 2500 + 255) / 256, 256>>>();
    k_bnprep<<<2, 256>>>(bn1_g, bn1_b, bn1_m, bn1_v, bn2_g, bn2_b, bn2_m, bn2_v);

    // ---- Winograd conv layer ----
    auto wlayer = [&](const uint32_t* in, size_t uoff, const float* bias,
                      const float* bnsc, const float* bnsh, const uint32_t* resid,
                      uint32_t* o, int T, int Cout, int relu, int ps) {
        int H = 2 * T;
        int NTpad = (T * T + 63) / 64 * 64;
        k_wino_in<<<(512 * NTpad + 255) / 256, 256>>>(in, p_v, H, T, NTpad);
        k_wgemm<<<dim3(NTpad / 64, Cout / 256, 16), 256, W_SMEM>>>(
            p_uhi + uoff, p_ulo + uoff, p_v, p_m,
            (long)Cout * 512, (long)512 * NTpad, (long)Cout * NTpad, NTpad);
        k_wino_out<<<(Cout * T * T + 255) / 256, 256>>>(
            p_m, o, bias, bnsc, bnsh, resid, Cout, T, NTpad, relu, ps);
    };

    // ---- EDSR upsampler (Winograd) ----
    wlayer(p_xs, U_HEAD, head_b, nullptr, nullptr, nullptr, p_h, 25, 512, 0, 0);
    cudaMemcpyAsync(p_r, p_h, (size_t)512 * 2500 * sizeof(uint32_t),
                    cudaMemcpyDeviceToDevice, 0);
    for (int i = 0; i < 8; i++) {
        wlayer(p_r, U_BODY(2 * i), body_b + (size_t)(2 * i) * 512,
               nullptr, nullptr, nullptr, p_tmp, 25, 512, 1, 0);
        wlayer(p_tmp, U_BODY(2 * i + 1), body_b + (size_t)(2 * i + 1) * 512,
               nullptr, nullptr, p_r, p_r, 25, 512, 0, 0);
    }
    wlayer(p_r, U_BTAIL, btail_b, nullptr, nullptr, p_h, p_tmp, 25, 512, 0, 0);
    wlayer(p_tmp, U_UP, up_b, nullptr, nullptr, nullptr, p_u, 25, 2048, 0, 1);
    wlayer(p_u, U_TAIL, tail_b, nullptr, nullptr, nullptr, p_y1, 50, 512, 0, 0);

    // ---- classifier ----
    wlayer(p_y1, U_C1, nullptr, p_bn, p_bn + 512, nullptr, p_y2, 50, 512, 1, 0);
    wlayer(p_y2, U_C2, nullptr, p_bn + 1024, p_bn + 1536, nullptr, p_y1, 50, 512, 1, 0);
    k_c3<<<(60000 + 255) / 256, 256>>>(c3_w, c3_b, out);
}

// round 13
// speedup vs baseline: 1.4184x; 1.4184x over previous
#include <cuda_runtime.h>
#include <cuda_bf16.h>
#include <math.h>
#include <stdint.h>

// ============================================================
// Static device scratch
// ============================================================
__device__ float g_x[512 * 1024];
__device__ float g_t[1024 * 512];
__device__ float g_qkv[1024 * 1024];
__device__ float g_attn[8 * 1024 * 1024];
__device__ float g_res[512 * 1024];
__device__ uint32_t g_xs[512 * 2500];
__device__ uint32_t g_h[512 * 2500];
__device__ uint32_t g_r[512 * 2500];
__device__ uint32_t g_tmp[512 * 2500];
__device__ uint32_t g_u[512 * 10000];
__device__ uint32_t g_y1[512 * 10000];
__device__ uint32_t g_y2[512 * 10000];
__device__ float g_bn[2048];

#define UL 4194304
#define U_HEAD  ((size_t)0)
#define U_BODY(i) ((size_t)(1 + (i)) * UL)
#define U_BTAIL ((size_t)17 * UL)
#define U_TAIL  ((size_t)18 * UL)
#define U_C1    ((size_t)19 * UL)
#define U_C2    ((size_t)20 * UL)
#define U_UP    ((size_t)21 * UL)
#define U_TOTAL ((size_t)21 * UL + 16777216)
__device__ __nv_bfloat16 g_uhi[U_TOTAL];
__device__ __nv_bfloat16 g_ulo[U_TOTAL];

__device__ uint32_t g_v[16 * 512 * 2560];
__device__ uint32_t g_m[16 * 512 * 2560];   // packed bf16x2 GEMM output

__device__ __nv_bfloat16 g_aqh[8 * 1536 * 512];
__device__ __nv_bfloat16 g_aql[8 * 1536 * 512];
__device__ __nv_bfloat16 g_aph[8 * 512 * 512];
__device__ __nv_bfloat16 g_apl[8 * 512 * 512];

// ============================================================
// Helpers
// ============================================================
__device__ __forceinline__ uint32_t smem_u32(const void* p) {
    uint32_t a;
    asm("{ .reg .u64 t; cvta.to.shared.u64 t, %1; cvt.u32.u64 %0, t; }"
        : "=r"(a) : "l"(p));
    return a;
}

__device__ __forceinline__ void cpasync16(uint32_t dst, const void* src) {
    asm volatile("cp.async.ca.shared.global [%0], [%1], 16;" :: "r"(dst), "l"(src));
}
#define CP_COMMIT asm volatile("cp.async.commit_group;" ::: "memory")
#define CP_WAIT0  asm volatile("cp.async.wait_group 0;" ::: "memory")

__device__ __forceinline__ void ldsm4(uint32_t addr, uint32_t* r) {
    asm volatile("ldmatrix.sync.aligned.m8n8.x4.shared.b16 {%0,%1,%2,%3}, [%4];"
                 : "=r"(r[0]), "=r"(r[1]), "=r"(r[2]), "=r"(r[3]) : "r"(addr));
}

__device__ __forceinline__ void mma16816(float* d, const uint32_t* a,
                                         uint32_t b0, uint32_t b1) {
    asm volatile(
        "mma.sync.aligned.m16n8k16.row.col.f32.bf16.bf16.f32 "
        "{%0,%1,%2,%3}, {%4,%5,%6,%7}, {%8,%9}, {%0,%1,%2,%3};"
        : "+f"(d[0]), "+f"(d[1]), "+f"(d[2]), "+f"(d[3])
        : "r"(a[0]), "r"(a[1]), "r"(a[2]), "r"(a[3]), "r"(b0), "r"(b1));
}

__device__ __forceinline__ void split2(float v0, float v1, uint32_t& hp, uint32_t& lp) {
    __nv_bfloat16 h0 = __float2bfloat16(v0), h1 = __float2bfloat16(v1);
    __nv_bfloat16 l0 = __float2bfloat16(v0 - __bfloat162float(h0));
    __nv_bfloat16 l1 = __float2bfloat16(v1 - __bfloat162float(h1));
    hp = (uint32_t)__bfloat16_as_ushort(h0) | ((uint32_t)__bfloat16_as_ushort(h1) << 16);
    lp = (uint32_t)__bfloat16_as_ushort(l0) | ((uint32_t)__bfloat16_as_ushort(l1) << 16);
}

__device__ __forceinline__ uint32_t packbf(float v) {
    __nv_bfloat16 h = __float2bfloat16(v);
    __nv_bfloat16 l = __float2bfloat16(v - __bfloat162float(h));
    return (uint32_t)__bfloat16_as_ushort(h) | ((uint32_t)__bfloat16_as_ushort(l) << 16);
}

__device__ __forceinline__ float unpackbf(uint32_t p) {
    return __bfloat162float(__ushort_as_bfloat16((unsigned short)(p & 0xffff))) +
           __bfloat162float(__ushort_as_bfloat16((unsigned short)(p >> 16)));
}

// ============================================================
// Weight prep
// ============================================================
__global__ void k_wwino(const float* __restrict__ w, __nv_bfloat16* __restrict__ uhi,
                        __nv_bfloat16* __restrict__ ulo, int Cout, int Cin) {
    int idx = blockIdx.x * 256 + threadIdx.x;
    if (idx >= Cout * Cin) return;
    int co = idx / Cin, ci = idx - co * Cin;
    const float* gp = w + (size_t)idx * 9;
    float g0 = gp[0], g1 = gp[1], g2 = gp[2];
    float g3 = gp[3], g4 = gp[4], g5 = gp[5];
    float g6 = gp[6], g7 = gp[7], g8 = gp[8];
    float t[4][3];
    t[0][0] = g0; t[0][1] = g1; t[0][2] = g2;
    t[1][0] = 0.5f * (g0 + g3 + g6); t[1][1] = 0.5f * (g1 + g4 + g7); t[1][2] = 0.5f * (g2 + g5 + g8);
    t[2][0] = 0.5f * (g0 - g3 + g6); t[2][1] = 0.5f * (g1 - g4 + g7); t[2][2] = 0.5f * (g2 - g5 + g8);
    t[3][0] = g6; t[3][1] = g7; t[3][2] = g8;
#pragma unroll
    for (int i = 0; i < 4; i++) {
        float a0 = t[i][0], a1 = t[i][1], a2 = t[i][2];
        float u[4];
        u[0] = a0;
        u[1] = 0.5f * (a0 + a1 + a2);
        u[2] = 0.5f * (a0 - a1 + a2);
        u[3] = a2;
#pragma unroll
        for (int j = 0; j < 4; j++) {
            int p = i * 4 + j;
            size_t o = (size_t)p * Cout * Cin + (size_t)co * Cin + ci;
            float v = u[j];
            __nv_bfloat16 h = __float2bfloat16(v);
            uhi[o] = h;
            ulo[o] = __float2bfloat16(v - __bfloat162float(h));
        }
    }
}

__global__ void k_wtq(const float* __restrict__ src, __nv_bfloat16* __restrict__ hi,
                      __nv_bfloat16* __restrict__ lo) {
    int idx = blockIdx.x * 256 + threadIdx.x;
    if (idx >= 8 * 1536 * 512) return;
    int blk = idx / (1536 * 512), r = idx - blk * (1536 * 512);
    int f = r >> 9, c = r & 511;
    float v = src[(size_t)blk * 512 * 1536 + c * 1536 + f];
    __nv_bfloat16 h = __float2bfloat16(v);
    hi[idx] = h;
    lo[idx] = __float2bfloat16(v - __bfloat162float(h));
}

__global__ void k_wtp(const float* __restrict__ src, __nv_bfloat16* __restrict__ hi,
                      __nv_bfloat16* __restrict__ lo) {
    int idx = blockIdx.x * 256 + threadIdx.x;
    if (idx >= 8 * 512 * 512) return;
    int blk = idx / (512 * 512), r = idx - blk * (512 * 512);
    int f = r >> 9, c = r & 511;
    float v = src[(size_t)blk * 512 * 512 + c * 512 + f];
    __nv_bfloat16 h = __float2bfloat16(v);
    hi[idx] = h;
    lo[idx] = __float2bfloat16(v - __bfloat162float(h));
}

// ============================================================
// Winograd input transform
// ============================================================
__global__ void k_wino_in(const uint32_t* __restrict__ in, uint32_t* __restrict__ V,
                          int H, int T, int NTpad) {
    int idx = blockIdx.x * 256 + threadIdx.x;
    if (idx >= 512 * NTpad) return;
    int c = idx / NTpad, t = idx - c * NTpad;
    size_t pstride = (size_t)512 * NTpad;
    if (t >= T * T) {
#pragma unroll
        for (int p = 0; p < 16; p++) V[(size_t)p * pstride + idx] = 0;
        return;
    }
    int ty = t / T, tx = t - ty * T;
    int r0 = 2 * ty - 1, c0 = 2 * tx - 1;
    const uint32_t* ip = in + (size_t)c * H * H;
    float d[4][4];
#pragma unroll
    for (int i = 0; i < 4; i++) {
        int rr = r0 + i;
        bool rv = (unsigned)rr < (unsigned)H;
#pragma unroll
        for (int j = 0; j < 4; j++) {
            int cc = c0 + j;
            d[i][j] = (rv && (unsigned)cc < (unsigned)H) ? unpackbf(ip[rr * H + cc]) : 0.f;
        }
    }
    float e[4][4];
#pragma unroll
    for (int j = 0; j < 4; j++) {
        e[0][j] = d[0][j] - d[2][j];
        e[1][j] = d[1][j] + d[2][j];
        e[2][j] = d[2][j] - d[1][j];
        e[3][j] = d[1][j] - d[3][j];
    }
#pragma unroll
    for (int i = 0; i < 4; i++) {
        float f0 = e[i][0] - e[i][2];
        float f1 = e[i][1] + e[i][2];
        float f2 = e[i][2] - e[i][1];
        float f3 = e[i][1] - e[i][3];
        V[(size_t)(i * 4 + 0) * pstride + idx] = packbf(f0);
        V[(size_t)(i * 4 + 1) * pstride + idx] = packbf(f1);
        V[(size_t)(i * 4 + 2) * pstride + idx] = packbf(f2);
        V[(size_t)(i * 4 + 3) * pstride + idx] = packbf(f3);
    }
}

// ============================================================
// Shared smem layout for GEMMs (R11 proven)
// ============================================================
#define PITCH 80
#define OFF_ALO (128 * PITCH)
#define OFF_BHI (2 * 128 * PITCH)
#define OFF_BLO (OFF_BHI + 64 * PITCH)
#define STAGE   (OFF_BLO + 64 * PITCH)   // 30720
#define SMEM_DYN (2 * STAGE)             // 61440

// ============================================================
// Winograd batched GEMM (R11 proven M=128 x N=64 tile), K=512.
// Output written as packed bf16x2.
// ============================================================
__global__ __launch_bounds__(256, 2)
void k_wgemm(const __nv_bfloat16* __restrict__ Ahi, const __nv_bfloat16* __restrict__ Alo,
             const uint32_t* __restrict__ Bp, uint32_t* __restrict__ outg,
             long aoz, long boz, long coz, int ldb) {
    extern __shared__ char sm[];
    int tid = threadIdx.x, wid = tid >> 5, lane = tid & 31;
    int n0 = blockIdx.x * 64, m0 = blockIdx.y * 128, z = blockIdx.z;
    uint32_t sb = smem_u32(sm);

    int arow = tid >> 1, aseg = tid & 1;
    const __nv_bfloat16* whp = Ahi + (size_t)z * aoz + (size_t)(m0 + arow) * 512 + aseg * 16;
    const __nv_bfloat16* wlp = Alo + (size_t)z * aoz + (size_t)(m0 + arow) * 512 + aseg * 16;
    uint32_t a_off = arow * PITCH + aseg * 32;

    int bpix = tid & 63, bkg = tid >> 6;
    const uint32_t* bbase = Bp + (size_t)z * boz + n0 + bpix;
    uint32_t b_off = OFF_BHI + bpix * PITCH + bkg * 16;

    uint32_t rBp[8];

    auto a_issue = [&](int ch, int buf) {
        int kk = ch << 5;
        uint32_t d0 = sb + a_off + buf * STAGE;
        cpasync16(d0, whp + kk);
        cpasync16(d0 + 16, whp + kk + 8);
        cpasync16(d0 + OFF_ALO, wlp + kk);
        cpasync16(d0 + OFF_ALO + 16, wlp + kk + 8);
        CP_COMMIT;
    };
    auto b_load = [&](int ch) {
        int kk = ch << 5;
#pragma unroll
        for (int j = 0; j < 8; j++)
            rBp[j] = bbase[(size_t)(kk + bkg * 8 + j) * ldb];
    };
    auto b_store = [&](int buf) {
        uint32_t bo = buf * STAGE;
#pragma unroll
        for (int j = 0; j < 8; j += 2) {
            uint32_t hp = __byte_perm(rBp[j], rBp[j + 1], 0x5410);
            uint32_t lp = __byte_perm(rBp[j], rBp[j + 1], 0x7632);
            *(uint32_t*)(sm + (b_off - OFF_BHI) + OFF_BHI + bo + j * 2) = hp;
            *(uint32_t*)(sm + (b_off - OFF_BHI) + OFF_BLO + bo + j * 2) = lp;
        }
    };

    int warp_m = wid & 3, warp_n = wid >> 2;
    uint32_t a_ld = sb + (warp_m * 32 + (lane & 15)) * PITCH + (lane >> 4) * 16;
    uint32_t b_ld = sb + OFF_BHI + (warp_n * 32 + (lane & 15)) * PITCH + (lane >> 4) * 16;

    float acc[2][4][4];
#pragma unroll
    for (int i = 0; i < 2; i++)
#pragma unroll
        for (int j = 0; j < 4; j++)
#pragma unroll
            for (int e = 0; e < 4; e++) acc[i][j][e] = 0.f;

    a_issue(0, 0);
    b_load(0);
    b_store(0);
    CP_WAIT0;
    __syncthreads();

    for (int ch = 0; ch < 16; ch++) {
        if (ch < 15) {
            a_issue(ch + 1, (ch + 1) & 1);
            b_load(ch + 1);
        }
        uint32_t bo = (ch & 1) * STAGE;
#pragma unroll
        for (int ks = 0; ks < 2; ks++) {
            uint32_t Ah[2][4], Al[2][4], Bh[2][4], Bl[2][4];
#pragma unroll
            for (int mt = 0; mt < 2; mt++) {
                ldsm4(a_ld + bo + mt * (16 * PITCH) + ks * 32, Ah[mt]);
                ldsm4(a_ld + bo + OFF_ALO + mt * (16 * PITCH) + ks * 32, Al[mt]);
            }
#pragma unroll
            for (int gq = 0; gq < 2; gq++) {
                ldsm4(b_ld + bo + gq * (16 * PITCH) + ks * 32, Bh[gq]);
                ldsm4(b_ld + bo + (OFF_BLO - OFF_BHI) + gq * (16 * PITCH) + ks * 32, Bl[gq]);
            }
#pragma unroll
            for (int mt = 0; mt < 2; mt++)
#pragma unroll
                for (int nt = 0; nt < 4; nt++) {
                    int gq = nt >> 1, idx = nt & 1;
                    uint32_t bh0 = Bh[gq][idx], bh1 = Bh[gq][idx + 2];
                    uint32_t bl0 = Bl[gq][idx], bl1 = Bl[gq][idx + 2];
                    mma16816(acc[mt][nt], Ah[mt], bh0, bh1);
                    mma16816(acc[mt][nt], Ah[mt], bl0, bl1);
                    mma16816(acc[mt][nt], Al[mt], bh0, bh1);
                }
        }
        if (ch < 15) {
            b_store((ch + 1) & 1);
            CP_WAIT0;
            __syncthreads();
        }
    }

    uint32_t* op = outg + (size_t)z * coz;
#pragma unroll
    for (int mt = 0; mt < 2; mt++) {
#pragma unroll
        for (int half = 0; half < 2; half++) {
            int co = m0 + warp_m * 32 + mt * 16 + (lane >> 2) + half * 8;
#pragma unroll
            for (int nt = 0; nt < 4; nt++) {
#pragma unroll
                for (int e = 0; e < 2; e++) {
                    int p = n0 + warp_n * 32 + nt * 8 + (lane & 3) * 2 + e;
                    op[(size_t)co * ldb + p] = packbf(acc[mt][nt][half * 2 + e]);
                }
            }
        }
    }
}

// ============================================================
// Winograd output transform (fused epilogue), packed-M input
// ============================================================
__global__ void k_wino_out(const uint32_t* __restrict__ Mb, uint32_t* __restrict__ out,
                           const float* __restrict__ bias,
                           const float* __restrict__ bnsc, const float* __restrict__ bnsh,
                           const uint32_t* __restrict__ resid,
                           int Cout, int T, int NTpad, int relu, int ps) {
    int idx = blockIdx.x * 256 + threadIdx.x;
    if (idx >= Cout * T * T) return;
    int co = idx / (T * T), t = idx - co * (T * T);
    int ty = t / T, tx = t - ty * T;
    int H = 2 * T, P = H * H;
    size_t pstride = (size_t)Cout * NTpad;
    const uint32_t* mp = Mb + (size_t)co * NTpad + t;
    float m[4][4];
#pragma unroll
    for (int i = 0; i < 4; i++)
#pragma unroll
        for (int j = 0; j < 4; j++)
            m[i][j] = unpackbf(mp[(size_t)(i * 4 + j) * pstride]);
    float s0[4], s1[4];
#pragma unroll
    for (int j = 0; j < 4; j++) {
        s0[j] = m[0][j] + m[1][j] + m[2][j];
        s1[j] = m[1][j] - m[2][j] - m[3][j];
    }
    float y[2][2];
    y[0][0] = s0[0] + s0[1] + s0[2];
    y[0][1] = s0[1] - s0[2] - s0[3];
    y[1][0] = s1[0] + s1[1] + s1[2];
    y[1][1] = s1[1] - s1[2] - s1[3];

    float bv = bias ? bias[co] : 0.f;
    float sc = bnsc ? bnsc[co] : 1.f;
    float sh = bnsh ? bnsh[co] : 0.f;
#pragma unroll
    for (int i = 0; i < 2; i++) {
#pragma unroll
        for (int j = 0; j < 2; j++) {
            int yy = 2 * ty + i, xx = 2 * tx + j;
            int pix = yy * H + xx;
            float v = y[i][j] + bv;
            if (bnsc) v = v * sc + sh;
            if (resid) v += unpackbf(resid[(size_t)co * P + pix]);
            if (relu) v = fmaxf(v, 0.f);
            uint32_t pk = packbf(v);
            if (ps) {
                int c = co >> 2, ry = (co >> 1) & 1, rx = co & 1;
                out[(size_t)c * (4 * P) + (size_t)(2 * yy + ry) * (2 * H) + 2 * xx + rx] = pk;
            } else {
                out[(size_t)co * P + pix] = pk;
            }
        }
    }
}

// ============================================================
// Attention tensor GEMM (unchanged, proven)
// ============================================================
template <int AM, int TRANS>
__global__ __launch_bounds__(256, 2)
void k_agemm(const __nv_bfloat16* __restrict__ Ahi, const __nv_bfloat16* __restrict__ Alo,
             const float* __restrict__ Af, const float* __restrict__ Bfg,
             float* __restrict__ outg, const float* __restrict__ bias,
             const float* __restrict__ resid,
             long aoz, long boz, long coz,
             int K, int lda, int ldb, int ldo, int Nn, float scale) {
    extern __shared__ char sm[];
    int tid = threadIdx.x, wid = tid >> 5, lane = tid & 31;
    int n0 = blockIdx.x * 64, m0 = blockIdx.y * 128, z = blockIdx.z;
    uint32_t sb = smem_u32(sm);
    int NCH = K >> 5;

    const float* Bf = Bfg + (size_t)z * boz;
    float* outp = outg + (size_t)z * coz;

    int arow = tid >> 1, aseg = tid & 1;
    int krow = tid >> 3, mseg = tid & 7;
    const __nv_bfloat16 *whp = nullptr, *wlp = nullptr;
    const float* afp = nullptr;
    if constexpr (AM == 0) {
        whp = Ahi + (size_t)z * aoz + (size_t)(m0 + arow) * lda + aseg * 16;
        wlp = Alo + (size_t)z * aoz + (size_t)(m0 + arow) * lda + aseg * 16;
    } else if constexpr (AM == 1) {
        afp = Af + (size_t)z * aoz + (size_t)krow * lda + m0 + mseg * 16;
    } else {
        afp = Af + (size_t)z * aoz + (size_t)(m0 + arow) * lda + aseg * 16;
    }
    uint32_t a_off = arow * PITCH + aseg * 32;

    int bpix = tid & 63, bkg = tid >> 6;
    uint32_t b_off = OFF_BHI + bpix * PITCH + bkg * 16;

    uint4 rAh[2], rAl[2];
    float rA[16];
    float rB[8];

    auto load_gmem = [&](int ch) {
        int kk = ch << 5;
        if constexpr (AM == 0) {
            rAh[0] = *(const uint4*)(whp + kk);
            rAh[1] = *(const uint4*)(whp + kk + 8);
            rAl[0] = *(const uint4*)(wlp + kk);
            rAl[1] = *(const uint4*)(wlp + kk + 8);
        } else if constexpr (AM == 1) {
            const float* p = afp + (size_t)kk * lda;
            *(float4*)(rA + 0) = *(const float4*)(p + 0);
            *(float4*)(rA + 4) = *(const float4*)(p + 4);
            *(float4*)(rA + 8) = *(const float4*)(p + 8);
            *(float4*)(rA + 12) = *(const float4*)(p + 12);
        } else {
            const float* p = afp + kk;
            *(float4*)(rA + 0) = *(const float4*)(p + 0);
            *(float4*)(rA + 4) = *(const float4*)(p + 4);
            *(float4*)(rA + 8) = *(const float4*)(p + 8);
            *(float4*)(rA + 12) = *(const float4*)(p + 12);
        }
#pragma unroll
        for (int j = 0; j < 8; j++)
            rB[j] = Bf[(size_t)(kk + bkg * 8 + j) * ldb + n0 + bpix];
    };

    auto store_smem = [&](int buf) {
        uint32_t bo = buf * STAGE;
        if constexpr (AM == 0) {
            *(uint4*)(sm + a_off + bo) = rAh[0];
            *(uint4*)(sm + a_off + bo + 16) = rAh[1];
            *(uint4*)(sm + a_off + bo + OFF_ALO) = rAl[0];
            *(uint4*)(sm + a_off + bo + OFF_ALO + 16) = rAl[1];
        } else if constexpr (AM == 1) {
#pragma unroll
            for (int j = 0; j < 16; j++) {
                float v = rA[j];
                __nv_bfloat16 h = __float2bfloat16(v);
                __nv_bfloat16 l = __float2bfloat16(v - __bfloat162float(h));
                uint32_t off = (mseg * 16 + j) * PITCH + krow * 2;
                *(__nv_bfloat16*)(sm + bo + off) = h;
                *(__nv_bfloat16*)(sm + bo + OFF_ALO + off) = l;
            }
        } else {
            uint32_t hp[8], lp[8];
#pragma unroll
            for (int j = 0; j < 8; j++) split2(rA[2 * j], rA[2 * j + 1], hp[j], lp[j]);
            *(uint4*)(sm + bo + a_off) = *(uint4*)hp;
            *(uint4*)(sm + bo + a_off + 16) = *(uint4*)(hp + 4);
            *(uint4*)(sm + bo + OFF_ALO + a_off) = *(uint4*)lp;
            *(uint4*)(sm + bo + OFF_ALO + a_off + 16) = *(uint4*)(lp + 4);
        }
#pragma unroll
        for (int j = 0; j < 8; j += 2) {
            uint32_t hp, lp;
            split2(rB[j], rB[j + 1], hp, lp);
            *(uint32_t*)(sm + (b_off - OFF_BHI) + OFF_BHI + bo + j * 2) = hp;
            *(uint32_t*)(sm + (b_off - OFF_BHI) + OFF_BLO + bo + j * 2) = lp;
        }
    };

    int warp_m = wid & 3, warp_n = wid >> 2;
    uint32_t a_ld = sb + (warp_m * 32 + (lane & 15)) * PITCH + (lane >> 4) * 16;
    uint32_t b_ld = sb + OFF_BHI + (warp_n * 32 + (lane & 15)) * PITCH + (lane >> 4) * 16;

    float acc[2][4][4];
#pragma unroll
    for (int i = 0; i < 2; i++)
#pragma unroll
        for (int j = 0; j < 4; j++)
#pragma unroll
            for (int e = 0; e < 4; e++) acc[i][j][e] = 0.f;

    load_gmem(0);
    store_smem(0);
    __syncthreads();

    for (int ch = 0; ch < NCH; ch++) {
        if (ch + 1 < NCH) load_gmem(ch + 1);
        uint32_t bo = (ch & 1) * STAGE;
#pragma unroll
        for (int ks = 0; ks < 2; ks++) {
            uint32_t Ah[2][4], Al[2][4], Bh[2][4], Bl[2][4];
#pragma unroll
            for (int mt = 0; mt < 2; mt++) {
                ldsm4(a_ld + bo + mt * (16 * PITCH) + ks * 32, Ah[mt]);
                ldsm4(a_ld + bo + OFF_ALO + mt * (16 * PITCH) + ks * 32, Al[mt]);
            }
#pragma unroll
            for (int gq = 0; gq < 2; gq++) {
                ldsm4(b_ld + bo + gq * (16 * PITCH) + ks * 32, Bh[gq]);
                ldsm4(b_ld + bo + (OFF_BLO - OFF_BHI) + gq * (16 * PITCH) + ks * 32, Bl[gq]);
            }
#pragma unroll
            for (int mt = 0; mt < 2; mt++)
#pragma unroll
                for (int nt = 0; nt < 4; nt++) {
                    int gq = nt >> 1, idx = nt & 1;
                    uint32_t bh0 = Bh[gq][idx], bh1 = Bh[gq][idx + 2];
                    uint32_t bl0 = Bl[gq][idx], bl1 = Bl[gq][idx + 2];
                    mma16816(acc[mt][nt], Ah[mt], bh0, bh1);
                    mma16816(acc[mt][nt], Ah[mt], bl0, bl1);
                    mma16816(acc[mt][nt], Al[mt], bh0, bh1);
                }
        }
        if (ch + 1 < NCH) {
            store_smem((ch + 1) & 1);
            __syncthreads();
        }
    }

#pragma unroll
    for (int mt = 0; mt < 2; mt++) {
#pragma unroll
        for (int half = 0; half < 2; half++) {
            int co = m0 + warp_m * 32 + mt * 16 + (lane >> 2) + half * 8;
            float bv = bias ? bias[co] : 0.f;
#pragma unroll
            for (int nt = 0; nt < 4; nt++) {
#pragma unroll
                for (int e = 0; e < 2; e++) {
                    int p = n0 + warp_n * 32 + nt * 8 + (lane & 3) * 2 + e;
                    if (p >= Nn) continue;
                    float v = acc[mt][nt][half * 2 + e] * scale + bv;
                    if (resid) v += resid[(size_t)co * ldo + p];
                    if (TRANS) outp[(size_t)p * ldo + co] = v;
                    else outp[(size_t)co * ldo + p] = v;
                }
            }
        }
    }
}

// ============================================================
// Softmax
// ============================================================
__global__ __launch_bounds__(256)
void k_softmax() {
    float* p = g_attn + (size_t)blockIdx.x * 1024;
    int tid = threadIdx.x;
    float4 v = *(float4*)(p + tid * 4);
    float mx = fmaxf(fmaxf(v.x, v.y), fmaxf(v.z, v.w));
#pragma unroll
    for (int o = 16; o > 0; o >>= 1) mx = fmaxf(mx, __shfl_xor_sync(0xffffffffu, mx, o));
    __shared__ float smx[8], ssm[8];
    if ((tid & 31) == 0) smx[tid >> 5] = mx;
    __syncthreads();
    mx = smx[0];
#pragma unroll
    for (int i = 1; i < 8; i++) mx = fmaxf(mx, smx[i]);
    float e0 = expf(v.x - mx), e1 = expf(v.y - mx), e2 = expf(v.z - mx), e3 = expf(v.w - mx);
    float s = e0 + e1 + e2 + e3;
#pragma unroll
    for (int o = 16; o > 0; o >>= 1) s += __shfl_xor_sync(0xffffffffu, s, o);
    if ((tid & 31) == 0) ssm[tid >> 5] = s;
    __syncthreads();
    s = ssm[0] + ssm[1] + ssm[2] + ssm[3] + ssm[4] + ssm[5] + ssm[6] + ssm[7];
    float inv = 1.f / s;
    *(float4*)(p + tid * 4) = make_float4(e0 * inv, e1 * inv, e2 * inv, e3 * inv);
}

// ============================================================
// Grid sample, BN fold, c3
// ============================================================
__device__ __forceinline__ int map_idx(int o, int size, bool* valid) {
    float vv = -49.f + 2.f * (float)o;
    float gg = (vv + 51.2f) / 102.4f * 2.f - 1.f;
    float f = ((gg + 1.f) * (float)size - 1.f) * 0.5f;
    int ii = (int)rintf(f);
    *valid = (ii >= 0) && (ii < size);
    return min(max(ii, 0), size - 1);
}

__global__ void k_gridsample() {
    int idx = blockIdx.x * 256 + threadIdx.x;
    if (idx >= 512 * 2500) return;
    int c = idx / 2500, p = idx - c * 2500;
    int oy = p / 50, ox = p - oy * 50;
    bool vy, vx;
    int iy = map_idx(oy, 32, &vy);
    int ix = map_idx(ox, 32, &vx);
    float v = (vy && vx) ? g_x[(size_t)c * 1024 + iy * 32 + ix] : 0.f;
    g_xs[idx] = packbf(v);
}

__global__ void k_bnprep(const float* g1, const float* b1, const float* m1, const float* v1,
                         const float* g2, const float* b2, const float* m2, const float* v2) {
    int c = blockIdx.x * 256 + threadIdx.x;
    if (c >= 512) return;
    float s1 = g1[c] / sqrtf(v1[c] + 1e-5f);
    g_bn[c] = s1;
    g_bn[512 + c] = b1[c] - m1[c] * s1;
    float s2 = g2[c] / sqrtf(v2[c] + 1e-5f);
    g_bn[1024 + c] = s2;
    g_bn[1536 + c] = b2[c] - m2[c] * s2;
}

__global__ void k_c3(const float* __restrict__ w, const float* __restrict__ b,
                     float* __restrict__ out) {
    int idx = blockIdx.x * 256 + threadIdx.x;
    if (idx >= 60000) return;
    int cls = idx / 10000, p = idx - cls * 10000;
    const float* wr = w + cls * 512;
    float s = b[cls];
#pragma unroll 4
    for (int c = 0; c < 512; c++) s += unpackbf(g_y1[(size_t)c * 10000 + p]) * wr[c];
    out[idx] = 1.f / (1.f + expf(-s));
}

// ============================================================
// Host orchestration
// ============================================================
extern "C" void kernel_launch(void* const* d_in, const int* in_sizes, int n_in,
                              void* d_out, int out_size) {
    const float* x       = (const float*)d_in[0];
    const float* qkv_w   = (const float*)d_in[1];
    const float* proj_w  = (const float*)d_in[2];
    const float* proj_b  = (const float*)d_in[3];
    const float* head_w  = (const float*)d_in[4];
    const float* head_b  = (const float*)d_in[5];
    const float* body_w  = (const float*)d_in[6];
    const float* body_b  = (const float*)d_in[7];
    const float* btail_w = (const float*)d_in[8];
    const float* btail_b = (const float*)d_in[9];
    const float* up_w    = (const float*)d_in[10];
    const float* up_b    = (const float*)d_in[11];
    const float* tail_w  = (const float*)d_in[12];
    const float* tail_b  = (const float*)d_in[13];
    const float* c1_w    = (const float*)d_in[14];
    const float* bn1_g   = (const float*)d_in[15];
    const float* bn1_b   = (const float*)d_in[16];
    const float* bn1_m   = (const float*)d_in[17];
    const float* bn1_v   = (const float*)d_in[18];
    const float* c2_w    = (const float*)d_in[19];
    const float* bn2_g   = (const float*)d_in[20];
    const float* bn2_b   = (const float*)d_in[21];
    const float* bn2_m   = (const float*)d_in[22];
    const float* bn2_v   = (const float*)d_in[23];
    const float* c3_w    = (const float*)d_in[24];
    const float* c3_b    = (const float*)d_in[25];
    float* out = (float*)d_out;

    float *p_x, *p_t, *p_qkv, *p_attn, *p_res, *p_bn;
    uint32_t *p_xs, *p_h, *p_r, *p_tmp, *p_u, *p_y1, *p_y2, *p_v, *p_m;
    __nv_bfloat16 *p_uhi, *p_ulo, *p_aqh, *p_aql, *p_aph, *p_apl;
    cudaGetSymbolAddress((void**)&p_x, g_x);
    cudaGetSymbolAddress((void**)&p_t, g_t);
    cudaGetSymbolAddress((void**)&p_qkv, g_qkv);
    cudaGetSymbolAddress((void**)&p_attn, g_attn);
    cudaGetSymbolAddress((void**)&p_res, g_res);
    cudaGetSymbolAddress((void**)&p_xs, g_xs);
    cudaGetSymbolAddress((void**)&p_h, g_h);
    cudaGetSymbolAddress((void**)&p_r, g_r);
    cudaGetSymbolAddress((void**)&p_tmp, g_tmp);
    cudaGetSymbolAddress((void**)&p_u, g_u);
    cudaGetSymbolAddress((void**)&p_y1, g_y1);
    cudaGetSymbolAddress((void**)&p_y2, g_y2);
    cudaGetSymbolAddress((void**)&p_bn, g_bn);
    cudaGetSymbolAddress((void**)&p_v, g_v);
    cudaGetSymbolAddress((void**)&p_m, g_m);
    cudaGetSymbolAddress((void**)&p_uhi, g_uhi);
    cudaGetSymbolAddress((void**)&p_ulo, g_ulo);
    cudaGetSymbolAddress((void**)&p_aqh, g_aqh);
    cudaGetSymbolAddress((void**)&p_aql, g_aql);
    cudaGetSymbolAddress((void**)&p_aph, g_aph);
    cudaGetSymbolAddress((void**)&p_apl, g_apl);

    cudaFuncSetAttribute(k_wgemm, cudaFuncAttributeMaxDynamicSharedMemorySize, SMEM_DYN);
    cudaFuncSetAttribute(k_agemm<0, 0>, cudaFuncAttributeMaxDynamicSharedMemorySize, SMEM_DYN);
    cudaFuncSetAttribute(k_agemm<0, 1>, cudaFuncAttributeMaxDynamicSharedMemorySize, SMEM_DYN);
    cudaFuncSetAttribute(k_agemm<1, 0>, cudaFuncAttributeMaxDynamicSharedMemorySize, SMEM_DYN);
    cudaFuncSetAttribute(k_agemm<2, 1>, cudaFuncAttributeMaxDynamicSharedMemorySize, SMEM_DYN);

    cudaMemcpyAsync(p_x, x, (size_t)512 * 1024 * sizeof(float),
                    cudaMemcpyDeviceToDevice, 0);

    // ---- weight prep ----
    auto wprep1 = [&](const float* w, size_t uoff, int Cout) {
        k_wwino<<<(Cout * 512 + 255) / 256, 256>>>(w, p_uhi + uoff, p_ulo + uoff, Cout, 512);
    };
    wprep1(head_w, U_HEAD, 512);
    k_wtq<<<(8 * 1536 * 512 + 255) / 256, 256>>>(qkv_w, p_aqh, p_aql);
    k_wtp<<<(8 * 512 * 512 + 255) / 256, 256>>>(proj_w, p_aph, p_apl);
    for (int i = 0; i < 16; i++)
        wprep1(body_w + (size_t)i * 512 * 512 * 9, U_BODY(i), 512);
    wprep1(btail_w, U_BTAIL, 512);
    wprep1(tail_w, U_TAIL, 512);
    wprep1(c1_w, U_C1, 512);
    wprep1(c2_w, U_C2, 512);
    k_wwino<<<(2048 * 512 + 255) / 256, 256>>>(up_w, p_uhi + U_UP, p_ulo + U_UP, 2048, 512);

    const float scale = 0.044194173824159216f;  // 512^-0.5

    // ---- 8 self-attention blocks ----
    for (int i = 0; i < 8; i++) {
        k_agemm<0, 0><<<dim3(16, 8, 1), 256, SMEM_DYN>>>(
            p_aqh + (size_t)i * 1536 * 512, p_aql + (size_t)i * 1536 * 512,
            nullptr, p_x, p_qkv, nullptr, nullptr,
            0, 0, 0, 512, 512, 1024, 1024, 1024, 1.f);
        k_agemm<0, 1><<<dim3(16, 4, 1), 256, SMEM_DYN>>>(
            p_aqh + (size_t)i * 1536 * 512 + (size_t)1024 * 512,
            p_aql + (size_t)i * 1536 * 512 + (size_t)1024 * 512,
            nullptr, p_x, p_t, nullptr, nullptr,
            0, 0, 0, 512, 512, 1024, 512, 1024, 1.f);
        k_agemm<1, 0><<<dim3(16, 8, 8), 256, SMEM_DYN>>>(
            nullptr, nullptr, p_qkv, p_qkv + (size_t)512 * 1024, p_attn,
            nullptr, nullptr,
            64 * 1024, 64 * 1024, 1l << 20, 64, 1024, 1024, 1024, 1024, scale);
        k_softmax<<<8192, 256>>>();
        k_agemm<2, 1><<<dim3(1, 8, 8), 256, SMEM_DYN>>>(
            nullptr, nullptr, p_attn, p_t, p_res, nullptr, nullptr,
            1l << 20, 64, 64 * 1024, 1024, 1024, 512, 1024, 64, 1.f);
        k_agemm<0, 0><<<dim3(16, 4, 1), 256, SMEM_DYN>>>(
            p_aph + (size_t)i * 512 * 512, p_apl + (size_t)i * 512 * 512,
            nullptr, p_res, p_x, proj_b + (size_t)i * 512, p_x,
            0, 0, 0, 512, 512, 1024, 1024, 1024, 1.f);
    }

    // ---- grid transform + BN fold ----
    k_gridsample<<<(512 * 2500 + 255) / 256, 256>>>();
    k_bnprep<<<2, 256>>>(bn1_g, bn1_b, bn1_m, bn1_v, bn2_g, bn2_b, bn2_m, bn2_v);

    // ---- Winograd conv layer ----
    auto wlayer = [&](const uint32_t* in, size_t uoff, const float* bias,
                      const float* bnsc, const float* bnsh, const uint32_t* resid,
                      uint32_t* o, int T, int Cout, int relu, int ps) {
        int H = 2 * T;
        int NTpad = (T * T + 63) / 64 * 64;
        k_wino_in<<<(512 * NTpad + 255) / 256, 256>>>(in, p_v, H, T, NTpad);
        k_wgemm<<<dim3(NTpad / 64, Cout / 128, 16), 256, SMEM_DYN>>>(
            p_uhi + uoff, p_ulo + uoff, p_v, p_m,
            (long)Cout * 512, (long)512 * NTpad, (long)Cout * NTpad, NTpad);
        k_wino_out<<<(Cout * T * T + 255) / 256, 256>>>(
            p_m, o, bias, bnsc, bnsh, resid, Cout, T, NTpad, relu, ps);
    };

    // ---- EDSR upsampler (Winograd) ----
    wlayer(p_xs, U_HEAD, head_b, nullptr, nullptr, nullptr, p_h, 25, 512, 0, 0);
    cudaMemcpyAsync(p_r, p_h, (size_t)512 * 2500 * sizeof(uint32_t),
                    cudaMemcpyDeviceToDevice, 0);
    for (int i = 0; i < 8; i++) {
        wlayer(p_r, U_BODY(2 * i), body_b + (size_t)(2 * i) * 512,
               nullptr, nullptr, nullptr, p_tmp, 25, 512, 1, 0);
        wlayer(p_tmp, U_BODY(2 * i + 1), body_b + (size_t)(2 * i + 1) * 512,
               nullptr, nullptr, p_r, p_r, 25, 512, 0, 0);
    }
    wlayer(p_r, U_BTAIL, btail_b, nullptr, nullptr, p_h, p_tmp, 25, 512, 0, 0);
    wlayer(p_tmp, U_UP, up_b, nullptr, nullptr, nullptr, p_u, 25, 2048, 0, 1);
    wlayer(p_u, U_TAIL, tail_b, nullptr, nullptr, nullptr, p_y1, 50, 512, 0, 0);

    // ---- classifier ----
    wlayer(p_y1, U_C1, nullptr, p_bn, p_bn + 512, nullptr, p_y2, 50, 512, 1, 0);
    wlayer(p_y2, U_C2, nullptr, p_bn + 1024, p_bn + 1536, nullptr, p_y1, 50, 512, 1, 0);
    k_c3<<<(60000 + 255) / 256, 256>>>(c3_w, c3_b, out);
}

// round 15
// speedup vs baseline: 1.4781x; 1.0421x over previous
#include <cuda_runtime.h>
#include <cuda_bf16.h>
#include <math.h>
#include <stdint.h>

// ============================================================
// Static device scratch
// ============================================================
__device__ float g_x[512 * 1024];
__device__ float g_t[1024 * 512];          // V token-major
__device__ float g_qkv[1024 * 1024];       // Q,K feature-major
__device__ uint32_t g_attn[8 * 1024 * 1024]; // packed bf16x2 S
__device__ float g_res[512 * 1024];
__device__ uint32_t g_xs[512 * 2500];
__device__ uint32_t g_h[512 * 2500];
__device__ uint32_t g_r[512 * 2500];
__device__ uint32_t g_tmp[512 * 2500];
__device__ uint32_t g_u[512 * 10000];
__device__ uint32_t g_y1[512 * 10000];
__device__ uint32_t g_y2[512 * 10000];
__device__ float g_bn[2048];

#define UL 4194304
#define U_HEAD  ((size_t)0)
#define U_BODY(i) ((size_t)(1 + (i)) * UL)
#define U_BTAIL ((size_t)17 * UL)
#define U_TAIL  ((size_t)18 * UL)
#define U_C1    ((size_t)19 * UL)
#define U_C2    ((size_t)20 * UL)
#define U_UP    ((size_t)21 * UL)
#define U_TOTAL ((size_t)21 * UL + 16777216)
__device__ __nv_bfloat16 g_uhi[U_TOTAL];
__device__ __nv_bfloat16 g_ulo[U_TOTAL];

__device__ uint32_t g_v[16 * 512 * 2560];
__device__ uint32_t g_m[16 * 512 * 2560];   // packed bf16x2 GEMM output

__device__ __nv_bfloat16 g_aqh[8 * 1536 * 512];
__device__ __nv_bfloat16 g_aql[8 * 1536 * 512];
__device__ __nv_bfloat16 g_aph[8 * 512 * 512];
__device__ __nv_bfloat16 g_apl[8 * 512 * 512];

// ============================================================
// Helpers
// ============================================================
__device__ __forceinline__ uint32_t smem_u32(const void* p) {
    uint32_t a;
    asm("{ .reg .u64 t; cvta.to.shared.u64 t, %1; cvt.u32.u64 %0, t; }"
        : "=r"(a) : "l"(p));
    return a;
}

__device__ __forceinline__ void cpasync16(uint32_t dst, const void* src) {
    asm volatile("cp.async.ca.shared.global [%0], [%1], 16;" :: "r"(dst), "l"(src));
}
#define CP_COMMIT asm volatile("cp.async.commit_group;" ::: "memory")
#define CP_WAIT0  asm volatile("cp.async.wait_group 0;" ::: "memory")

__device__ __forceinline__ void ldsm4(uint32_t addr, uint32_t* r) {
    asm volatile("ldmatrix.sync.aligned.m8n8.x4.shared.b16 {%0,%1,%2,%3}, [%4];"
                 : "=r"(r[0]), "=r"(r[1]), "=r"(r[2]), "=r"(r[3]) : "r"(addr));
}

__device__ __forceinline__ void mma16816(float* d, const uint32_t* a,
                                         uint32_t b0, uint32_t b1) {
    asm volatile(
        "mma.sync.aligned.m16n8k16.row.col.f32.bf16.bf16.f32 "
        "{%0,%1,%2,%3}, {%4,%5,%6,%7}, {%8,%9}, {%0,%1,%2,%3};"
        : "+f"(d[0]), "+f"(d[1]), "+f"(d[2]), "+f"(d[3])
        : "r"(a[0]), "r"(a[1]), "r"(a[2]), "r"(a[3]), "r"(b0), "r"(b1));
}

__device__ __forceinline__ void split2(float v0, float v1, uint32_t& hp, uint32_t& lp) {
    __nv_bfloat16 h0 = __float2bfloat16(v0), h1 = __float2bfloat16(v1);
    __nv_bfloat16 l0 = __float2bfloat16(v0 - __bfloat162float(h0));
    __nv_bfloat16 l1 = __float2bfloat16(v1 - __bfloat162float(h1));
    hp = (uint32_t)__bfloat16_as_ushort(h0) | ((uint32_t)__bfloat16_as_ushort(h1) << 16);
    lp = (uint32_t)__bfloat16_as_ushort(l0) | ((uint32_t)__bfloat16_as_ushort(l1) << 16);
}

__device__ __forceinline__ uint32_t packbf(float v) {
    __nv_bfloat16 h = __float2bfloat16(v);
    __nv_bfloat16 l = __float2bfloat16(v - __bfloat162float(h));
    return (uint32_t)__bfloat16_as_ushort(h) | ((uint32_t)__bfloat16_as_ushort(l) << 16);
}

__device__ __forceinline__ float unpackbf(uint32_t p) {
    return __bfloat162float(__ushort_as_bfloat16((unsigned short)(p & 0xffff))) +
           __bfloat162float(__ushort_as_bfloat16((unsigned short)(p >> 16)));
}

// ============================================================
// Weight prep
// ============================================================
__device__ __forceinline__ void wino_split_one(const float* gp, __nv_bfloat16* uhi,
                                               __nv_bfloat16* ulo, size_t base,
                                               size_t pstride) {
    float g0 = gp[0], g1 = gp[1], g2 = gp[2];
    float g3 = gp[3], g4 = gp[4], g5 = gp[5];
    float g6 = gp[6], g7 = gp[7], g8 = gp[8];
    float t[4][3];
    t[0][0] = g0; t[0][1] = g1; t[0][2] = g2;
    t[1][0] = 0.5f * (g0 + g3 + g6); t[1][1] = 0.5f * (g1 + g4 + g7); t[1][2] = 0.5f * (g2 + g5 + g8);
    t[2][0] = 0.5f * (g0 - g3 + g6); t[2][1] = 0.5f * (g1 - g4 + g7); t[2][2] = 0.5f * (g2 - g5 + g8);
    t[3][0] = g6; t[3][1] = g7; t[3][2] = g8;
#pragma unroll
    for (int i = 0; i < 4; i++) {
        float a0 = t[i][0], a1 = t[i][1], a2 = t[i][2];
        float u[4];
        u[0] = a0;
        u[1] = 0.5f * (a0 + a1 + a2);
        u[2] = 0.5f * (a0 - a1 + a2);
        u[3] = a2;
#pragma unroll
        for (int j = 0; j < 4; j++) {
            size_t o = base + (size_t)(i * 4 + j) * pstride;
            float v = u[j];
            __nv_bfloat16 h = __float2bfloat16(v);
            uhi[o] = h;
            ulo[o] = __float2bfloat16(v - __bfloat162float(h));
        }
    }
}

__global__ void k_wwino(const float* __restrict__ w, __nv_bfloat16* __restrict__ uhi,
                        __nv_bfloat16* __restrict__ ulo, int Cout, int Cin) {
    int idx = blockIdx.x * 256 + threadIdx.x;
    if (idx >= Cout * Cin) return;
    wino_split_one(w + (size_t)idx * 9, uhi, ulo, (size_t)idx, (size_t)Cout * Cin);
}

// batched: nl contiguous layers of 512x512x9; per-layer [16][512][512]
__global__ void k_wwinoN(const float* __restrict__ w, __nv_bfloat16* __restrict__ uhi,
                         __nv_bfloat16* __restrict__ ulo, int nl) {
    int idx = blockIdx.x * 256 + threadIdx.x;
    if (idx >= nl * 512 * 512) return;
    int layer = idx / (512 * 512), r = idx - layer * (512 * 512);
    wino_split_one(w + (size_t)idx * 9, uhi, ulo,
                   (size_t)layer * UL + (size_t)r, (size_t)512 * 512);
}

__global__ void k_wtq(const float* __restrict__ src, __nv_bfloat16* __restrict__ hi,
                      __nv_bfloat16* __restrict__ lo) {
    int idx = blockIdx.x * 256 + threadIdx.x;
    if (idx >= 8 * 1536 * 512) return;
    int blk = idx / (1536 * 512), r = idx - blk * (1536 * 512);
    int f = r >> 9, c = r & 511;
    float v = src[(size_t)blk * 512 * 1536 + c * 1536 + f];
    __nv_bfloat16 h = __float2bfloat16(v);
    hi[idx] = h;
    lo[idx] = __float2bfloat16(v - __bfloat162float(h));
}

__global__ void k_wtp(const float* __restrict__ src, __nv_bfloat16* __restrict__ hi,
                      __nv_bfloat16* __restrict__ lo) {
    int idx = blockIdx.x * 256 + threadIdx.x;
    if (idx >= 8 * 512 * 512) return;
    int blk = idx / (512 * 512), r = idx - blk * (512 * 512);
    int f = r >> 9, c = r & 511;
    float v = src[(size_t)blk * 512 * 512 + c * 512 + f];
    __nv_bfloat16 h = __float2bfloat16(v);
    hi[idx] = h;
    lo[idx] = __float2bfloat16(v - __bfloat162float(h));
}

// ============================================================
// Winograd input transform
// ============================================================
__global__ void k_wino_in(const uint32_t* __restrict__ in, uint32_t* __restrict__ V,
                          int H, int T, int NTpad) {
    int idx = blockIdx.x * 256 + threadIdx.x;
    if (idx >= 512 * NTpad) return;
    int c = idx / NTpad, t = idx - c * NTpad;
    size_t pstride = (size_t)512 * NTpad;
    if (t >= T * T) {
#pragma unroll
        for (int p = 0; p < 16; p++) V[(size_t)p * pstride + idx] = 0;
        return;
    }
    int ty = t / T, tx = t - ty * T;
    int r0 = 2 * ty - 1, c0 = 2 * tx - 1;
    const uint32_t* ip = in + (size_t)c * H * H;
    float d[4][4];
#pragma unroll
    for (int i = 0; i < 4; i++) {
        int rr = r0 + i;
        bool rv = (unsigned)rr < (unsigned)H;
#pragma unroll
        for (int j = 0; j < 4; j++) {
            int cc = c0 + j;
            d[i][j] = (rv && (unsigned)cc < (unsigned)H) ? unpackbf(ip[rr * H + cc]) : 0.f;
        }
    }
    float e[4][4];
#pragma unroll
    for (int j = 0; j < 4; j++) {
        e[0][j] = d[0][j] - d[2][j];
        e[1][j] = d[1][j] + d[2][j];
        e[2][j] = d[2][j] - d[1][j];
        e[3][j] = d[1][j] - d[3][j];
    }
#pragma unroll
    for (int i = 0; i < 4; i++) {
        float f0 = e[i][0] - e[i][2];
        float f1 = e[i][1] + e[i][2];
        float f2 = e[i][2] - e[i][1];
        float f3 = e[i][1] - e[i][3];
        V[(size_t)(i * 4 + 0) * pstride + idx] = packbf(f0);
        V[(size_t)(i * 4 + 1) * pstride + idx] = packbf(f1);
        V[(size_t)(i * 4 + 2) * pstride + idx] = packbf(f2);
        V[(size_t)(i * 4 + 3) * pstride + idx] = packbf(f3);
    }
}

// ============================================================
// Shared smem layout for GEMMs
// ============================================================
#define PITCH 80
#define OFF_ALO (128 * PITCH)
#define OFF_BHI (2 * 128 * PITCH)
#define OFF_BLO (OFF_BHI + 64 * PITCH)
#define STAGE   (OFF_BLO + 64 * PITCH)   // 30720
#define SMEM_DYN (2 * STAGE)             // 61440

// ============================================================
// Winograd batched GEMM (proven M=128 x N=64 tile), K=512.
// Packed bf16x2 output.
// ============================================================
__global__ __launch_bounds__(256, 2)
void k_wgemm(const __nv_bfloat16* __restrict__ Ahi, const __nv_bfloat16* __restrict__ Alo,
             const uint32_t* __restrict__ Bp, uint32_t* __restrict__ outg,
             long aoz, long boz, long coz, int ldb) {
    extern __shared__ char sm[];
    int tid = threadIdx.x, wid = tid >> 5, lane = tid & 31;
    int n0 = blockIdx.x * 64, m0 = blockIdx.y * 128, z = blockIdx.z;
    uint32_t sb = smem_u32(sm);

    int arow = tid >> 1, aseg = tid & 1;
    const __nv_bfloat16* whp = Ahi + (size_t)z * aoz + (size_t)(m0 + arow) * 512 + aseg * 16;
    const __nv_bfloat16* wlp = Alo + (size_t)z * aoz + (size_t)(m0 + arow) * 512 + aseg * 16;
    uint32_t a_off = arow * PITCH + aseg * 32;

    int bpix = tid & 63, bkg = tid >> 6;
    const uint32_t* bbase = Bp + (size_t)z * boz + n0 + bpix;
    uint32_t b_off = OFF_BHI + bpix * PITCH + bkg * 16;

    uint32_t rBp[8];

    auto a_issue = [&](int ch, int buf) {
        int kk = ch << 5;
        uint32_t d0 = sb + a_off + buf * STAGE;
        cpasync16(d0, whp + kk);
        cpasync16(d0 + 16, whp + kk + 8);
        cpasync16(d0 + OFF_ALO, wlp + kk);
        cpasync16(d0 + OFF_ALO + 16, wlp + kk + 8);
        CP_COMMIT;
    };
    auto b_load = [&](int ch) {
        int kk = ch << 5;
#pragma unroll
        for (int j = 0; j < 8; j++)
            rBp[j] = bbase[(size_t)(kk + bkg * 8 + j) * ldb];
    };
    auto b_store = [&](int buf) {
        uint32_t bo = buf * STAGE;
#pragma unroll
        for (int j = 0; j < 8; j += 2) {
            uint32_t hp = __byte_perm(rBp[j], rBp[j + 1], 0x5410);
            uint32_t lp = __byte_perm(rBp[j], rBp[j + 1], 0x7632);
            *(uint32_t*)(sm + (b_off - OFF_BHI) + OFF_BHI + bo + j * 2) = hp;
            *(uint32_t*)(sm + (b_off - OFF_BHI) + OFF_BLO + bo + j * 2) = lp;
        }
    };

    int warp_m = wid & 3, warp_n = wid >> 2;
    uint32_t a_ld = sb + (warp_m * 32 + (lane & 15)) * PITCH + (lane >> 4) * 16;
    uint32_t b_ld = sb + OFF_BHI + (warp_n * 32 + (lane & 15)) * PITCH + (lane >> 4) * 16;

    float acc[2][4][4];
#pragma unroll
    for (int i = 0; i < 2; i++)
#pragma unroll
        for (int j = 0; j < 4; j++)
#pragma unroll
            for (int e = 0; e < 4; e++) acc[i][j][e] = 0.f;

    a_issue(0, 0);
    b_load(0);
    b_store(0);
    CP_WAIT0;
    __syncthreads();

    for (int ch = 0; ch < 16; ch++) {
        if (ch < 15) {
            a_issue(ch + 1, (ch + 1) & 1);
            b_load(ch + 1);
        }
        uint32_t bo = (ch & 1) * STAGE;
#pragma unroll
        for (int ks = 0; ks < 2; ks++) {
            uint32_t Ah[2][4], Al[2][4], Bh[2][4], Bl[2][4];
#pragma unroll
            for (int mt = 0; mt < 2; mt++) {
                ldsm4(a_ld + bo + mt * (16 * PITCH) + ks * 32, Ah[mt]);
                ldsm4(a_ld + bo + OFF_ALO + mt * (16 * PITCH) + ks * 32, Al[mt]);
            }
#pragma unroll
            for (int gq = 0; gq < 2; gq++) {
                ldsm4(b_ld + bo + gq * (16 * PITCH) + ks * 32, Bh[gq]);
                ldsm4(b_ld + bo + (OFF_BLO - OFF_BHI) + gq * (16 * PITCH) + ks * 32, Bl[gq]);
            }
#pragma unroll
            for (int mt = 0; mt < 2; mt++)
#pragma unroll
                for (int nt = 0; nt < 4; nt++) {
                    int gq = nt >> 1, idx = nt & 1;
                    uint32_t bh0 = Bh[gq][idx], bh1 = Bh[gq][idx + 2];
                    uint32_t bl0 = Bl[gq][idx], bl1 = Bl[gq][idx + 2];
                    mma16816(acc[mt][nt], Ah[mt], bh0, bh1);
                    mma16816(acc[mt][nt], Ah[mt], bl0, bl1);
                    mma16816(acc[mt][nt], Al[mt], bh0, bh1);
                }
        }
        if (ch < 15) {
            b_store((ch + 1) & 1);
            CP_WAIT0;
            __syncthreads();
        }
    }

    uint32_t* op = outg + (size_t)z * coz;
#pragma unroll
    for (int mt = 0; mt < 2; mt++) {
#pragma unroll
        for (int half = 0; half < 2; half++) {
            int co = m0 + warp_m * 32 + mt * 16 + (lane >> 2) + half * 8;
#pragma unroll
            for (int nt = 0; nt < 4; nt++) {
#pragma unroll
                for (int e = 0; e < 2; e++) {
                    int p = n0 + warp_n * 32 + nt * 8 + (lane & 3) * 2 + e;
                    op[(size_t)co * ldb + p] = packbf(acc[mt][nt][half * 2 + e]);
                }
            }
        }
    }
}

// ============================================================
// Winograd output transform (fused epilogue), packed-M input
// ============================================================
__global__ void k_wino_out(const uint32_t* __restrict__ Mb, uint32_t* __restrict__ out,
                           const float* __restrict__ bias,
                           const float* __restrict__ bnsc, const float* __restrict__ bnsh,
                           const uint32_t* __restrict__ resid,
                           int Cout, int T, int NTpad, int relu, int ps) {
    int idx = blockIdx.x * 256 + threadIdx.x;
    if (idx >= Cout * T * T) return;
    int co = idx / (T * T), t = idx - co * (T * T);
    int ty = t / T, tx = t - ty * T;
    int H = 2 * T, P = H * H;
    size_t pstride = (size_t)Cout * NTpad;
    const uint32_t* mp = Mb + (size_t)co * NTpad + t;
    float m[4][4];
#pragma unroll
    for (int i = 0; i < 4; i++)
#pragma unroll
        for (int j = 0; j < 4; j++)
            m[i][j] = unpackbf(mp[(size_t)(i * 4 + j) * pstride]);
    float s0[4], s1[4];
#pragma unroll
    for (int j = 0; j < 4; j++) {
        s0[j] = m[0][j] + m[1][j] + m[2][j];
        s1[j] = m[1][j] - m[2][j] - m[3][j];
    }
    float y[2][2];
    y[0][0] = s0[0] + s0[1] + s0[2];
    y[0][1] = s0[1] - s0[2] - s0[3];
    y[1][0] = s1[0] + s1[1] + s1[2];
    y[1][1] = s1[1] - s1[2] - s1[3];

    float bv = bias ? bias[co] : 0.f;
    float sc = bnsc ? bnsc[co] : 1.f;
    float sh = bnsh ? bnsh[co] : 0.f;
#pragma unroll
    for (int i = 0; i < 2; i++) {
#pragma unroll
        for (int j = 0; j < 2; j++) {
            int yy = 2 * ty + i, xx = 2 * tx + j;
            int pix = yy * H + xx;
            float v = y[i][j] + bv;
            if (bnsc) v = v * sc + sh;
            if (resid) v += unpackbf(resid[(size_t)co * P + pix]);
            if (relu) v = fmaxf(v, 0.f);
            uint32_t pk = packbf(v);
            if (ps) {
                int c = co >> 2, ry = (co >> 1) & 1, rx = co & 1;
                out[(size_t)c * (4 * P) + (size_t)(2 * yy + ry) * (2 * H) + 2 * xx + rx] = pk;
            } else {
                out[(size_t)co * P + pix] = pk;
            }
        }
    }
}

// ============================================================
// Attention tensor GEMM.
// AM: 0 presplit bf16 [m][k]; 1 fp32 [k][m]; 2 fp32 [m][k]; 3 packed u32 [m][k]
// TRANS: 0 fp32 [m][n]; 1 fp32 [n][m]; 2 QKV route (co<1024 -> outp,
//        else out2[n][co-1024]); 3 packed u32 [m][n]
// ============================================================
template <int AM, int TRANS>
__global__ __launch_bounds__(256, 2)
void k_agemm(const __nv_bfloat16* __restrict__ Ahi, const __nv_bfloat16* __restrict__ Alo,
             const float* __restrict__ Af, const float* __restrict__ Bfg,
             float* __restrict__ outg, float* __restrict__ out2g,
             const float* __restrict__ bias, const float* __restrict__ resid,
             long aoz, long boz, long coz,
             int K, int lda, int ldb, int ldo, int Nn, float scale) {
    extern __shared__ char sm[];
    int tid = threadIdx.x, wid = tid >> 5, lane = tid & 31;
    int n0 = blockIdx.x * 64, m0 = blockIdx.y * 128, z = blockIdx.z;
    uint32_t sb = smem_u32(sm);
    int NCH = K >> 5;

    const float* Bf = Bfg + (size_t)z * boz;
    float* outp = outg + (size_t)z * coz;

    int arow = tid >> 1, aseg = tid & 1;
    int krow = tid >> 3, mseg = tid & 7;
    const __nv_bfloat16 *whp = nullptr, *wlp = nullptr;
    const float* afp = nullptr;
    const uint32_t* app = nullptr;
    if constexpr (AM == 0) {
        whp = Ahi + (size_t)z * aoz + (size_t)(m0 + arow) * lda + aseg * 16;
        wlp = Alo + (size_t)z * aoz + (size_t)(m0 + arow) * lda + aseg * 16;
    } else if constexpr (AM == 1) {
        afp = Af + (size_t)z * aoz + (size_t)krow * lda + m0 + mseg * 16;
    } else if constexpr (AM == 2) {
        afp = Af + (size_t)z * aoz + (size_t)(m0 + arow) * lda + aseg * 16;
    } else {
        app = (const uint32_t*)Af + (size_t)z * aoz + (size_t)(m0 + arow) * lda + aseg * 16;
    }
    uint32_t a_off = arow * PITCH + aseg * 32;

    int bpix = tid & 63, bkg = tid >> 6;
    uint32_t b_off = OFF_BHI + bpix * PITCH + bkg * 16;

    uint4 rAh[2], rAl[2];
    float rA[16];
    uint4 rAp[4];
    float rB[8];

    auto load_gmem = [&](int ch) {
        int kk = ch << 5;
        if constexpr (AM == 0) {
            rAh[0] = *(const uint4*)(whp + kk);
            rAh[1] = *(const uint4*)(whp + kk + 8);
            rAl[0] = *(const uint4*)(wlp + kk);
            rAl[1] = *(const uint4*)(wlp + kk + 8);
        } else if constexpr (AM == 1) {
            const float* p = afp + (size_t)kk * lda;
            *(float4*)(rA + 0) = *(const float4*)(p + 0);
            *(float4*)(rA + 4) = *(const float4*)(p + 4);
            *(float4*)(rA + 8) = *(const float4*)(p + 8);
            *(float4*)(rA + 12) = *(const float4*)(p + 12);
        } else if constexpr (AM == 2) {
            const float* p = afp + kk;
            *(float4*)(rA + 0) = *(const float4*)(p + 0);
            *(float4*)(rA + 4) = *(const float4*)(p + 4);
            *(float4*)(rA + 8) = *(const float4*)(p + 8);
            *(float4*)(rA + 12) = *(const float4*)(p + 12);
        } else {
            const uint4* p = (const uint4*)(app + kk);
            rAp[0] = p[0]; rAp[1] = p[1]; rAp[2] = p[2]; rAp[3] = p[3];
        }
#pragma unroll
        for (int j = 0; j < 8; j++)
            rB[j] = Bf[(size_t)(kk + bkg * 8 + j) * ldb + n0 + bpix];
    };

    auto store_smem = [&](int buf) {
        uint32_t bo = buf * STAGE;
        if constexpr (AM == 0) {
            *(uint4*)(sm + a_off + bo) = rAh[0];
            *(uint4*)(sm + a_off + bo + 16) = rAh[1];
            *(uint4*)(sm + a_off + bo + OFF_ALO) = rAl[0];
            *(uint4*)(sm + a_off + bo + OFF_ALO + 16) = rAl[1];
        } else if constexpr (AM == 1) {
#pragma unroll
            for (int j = 0; j < 16; j++) {
                float v = rA[j];
                __nv_bfloat16 h = __float2bfloat16(v);
                __nv_bfloat16 l = __float2bfloat16(v - __bfloat162float(h));
                uint32_t off = (mseg * 16 + j) * PITCH + krow * 2;
                *(__nv_bfloat16*)(sm + bo + off) = h;
                *(__nv_bfloat16*)(sm + bo + OFF_ALO + off) = l;
            }
        } else if constexpr (AM == 2) {
            uint32_t hp[8], lp[8];
#pragma unroll
            for (int j = 0; j < 8; j++) split2(rA[2 * j], rA[2 * j + 1], hp[j], lp[j]);
            *(uint4*)(sm + bo + a_off) = *(uint4*)hp;
            *(uint4*)(sm + bo + a_off + 16) = *(uint4*)(hp + 4);
            *(uint4*)(sm + bo + OFF_ALO + a_off) = *(uint4*)lp;
            *(uint4*)(sm + bo + OFF_ALO + a_off + 16) = *(uint4*)(lp + 4);
        } else {
            const uint32_t* w = (const uint32_t*)rAp;
            uint32_t hp[8], lp[8];
#pragma unroll
            for (int j = 0; j < 8; j++) {
                hp[j] = __byte_perm(w[2 * j], w[2 * j + 1], 0x5410);
                lp[j] = __byte_perm(w[2 * j], w[2 * j + 1], 0x7632);
            }
            *(uint4*)(sm + bo + a_off) = *(uint4*)hp;
            *(uint4*)(sm + bo + a_off + 16) = *(uint4*)(hp + 4);
            *(uint4*)(sm + bo + OFF_ALO + a_off) = *(uint4*)lp;
            *(uint4*)(sm + bo + OFF_ALO + a_off + 16) = *(uint4*)(lp + 4);
        }
#pragma unroll
        for (int j = 0; j < 8; j += 2) {
            uint32_t hp, lp;
            split2(rB[j], rB[j + 1], hp, lp);
            *(uint32_t*)(sm + (b_off - OFF_BHI) + OFF_BHI + bo + j * 2) = hp;
            *(uint32_t*)(sm + (b_off - OFF_BHI) + OFF_BLO + bo + j * 2) = lp;
        }
    };

    int warp_m = wid & 3, warp_n = wid >> 2;
    uint32_t a_ld = sb + (warp_m * 32 + (lane & 15)) * PITCH + (lane >> 4) * 16;
    uint32_t b_ld = sb + OFF_BHI + (warp_n * 32 + (lane & 15)) * PITCH + (lane >> 4) * 16;

    float acc[2][4][4];
#pragma unroll
    for (int i = 0; i < 2; i++)
#pragma unroll
        for (int j = 0; j < 4; j++)
#pragma unroll
            for (int e = 0; e < 4; e++) acc[i][j][e] = 0.f;

    load_gmem(0);
    store_smem(0);
    __syncthreads();

    for (int ch = 0; ch < NCH; ch++) {
        if (ch + 1 < NCH) load_gmem(ch + 1);
        uint32_t bo = (ch & 1) * STAGE;
#pragma unroll
        for (int ks = 0; ks < 2; ks++) {
            uint32_t Ah[2][4], Al[2][4], Bh[2][4], Bl[2][4];
#pragma unroll
            for (int mt = 0; mt < 2; mt++) {
                ldsm4(a_ld + bo + mt * (16 * PITCH) + ks * 32, Ah[mt]);
                ldsm4(a_ld + bo + OFF_ALO + mt * (16 * PITCH) + ks * 32, Al[mt]);
            }
#pragma unroll
            for (int gq = 0; gq < 2; gq++) {
                ldsm4(b_ld + bo + gq * (16 * PITCH) + ks * 32, Bh[gq]);
                ldsm4(b_ld + bo + (OFF_BLO - OFF_BHI) + gq * (16 * PITCH) + ks * 32, Bl[gq]);
            }
#pragma unroll
            for (int mt = 0; mt < 2; mt++)
#pragma unroll
                for (int nt = 0; nt < 4; nt++) {
                    int gq = nt >> 1, idx = nt & 1;
                    uint32_t bh0 = Bh[gq][idx], bh1 = Bh[gq][idx + 2];
                    uint32_t bl0 = Bl[gq][idx], bl1 = Bl[gq][idx + 2];
                    mma16816(acc[mt][nt], Ah[mt], bh0, bh1);
                    mma16816(acc[mt][nt], Ah[mt], bl0, bl1);
                    mma16816(acc[mt][nt], Al[mt], bh0, bh1);
                }
        }
        if (ch + 1 < NCH) {
            store_smem((ch + 1) & 1);
            __syncthreads();
        }
    }

#pragma unroll
    for (int mt = 0; mt < 2; mt++) {
#pragma unroll
        for (int half = 0; half < 2; half++) {
            int co = m0 + warp_m * 32 + mt * 16 + (lane >> 2) + half * 8;
            float bv = bias ? bias[co] : 0.f;
#pragma unroll
            for (int nt = 0; nt < 4; nt++) {
#pragma unroll
                for (int e = 0; e < 2; e++) {
                    int p = n0 + warp_n * 32 + nt * 8 + (lane & 3) * 2 + e;
                    if (p >= Nn) continue;
                    float v = acc[mt][nt][half * 2 + e] * scale + bv;
                    if (resid) v += resid[(size_t)co * ldo + p];
                    if constexpr (TRANS == 0) {
                        outp[(size_t)co * ldo + p] = v;
                    } else if constexpr (TRANS == 1) {
                        outp[(size_t)p * ldo + co] = v;
                    } else if constexpr (TRANS == 2) {
                        if (co < 1024) outp[(size_t)co * ldo + p] = v;
                        else out2g[(size_t)p * 512 + (co - 1024)] = v;
                    } else {
                        ((uint32_t*)outp)[(size_t)co * ldo + p] = packbf(v);
                    }
                }
            }
        }
    }
}

// ============================================================
// Softmax on packed bf16x2 rows
// ============================================================
__global__ __launch_bounds__(256)
void k_softmax() {
    uint32_t* p = g_attn + (size_t)blockIdx.x * 1024;
    int tid = threadIdx.x;
    uint4 pk = *(uint4*)(p + tid * 4);
    float v0 = unpackbf(pk.x), v1 = unpackbf(pk.y), v2 = unpackbf(pk.z), v3 = unpackbf(pk.w);
    float mx = fmaxf(fmaxf(v0, v1), fmaxf(v2, v3));
#pragma unroll
    for (int o = 16; o > 0; o >>= 1) mx = fmaxf(mx, __shfl_xor_sync(0xffffffffu, mx, o));
    __shared__ float smx[8], ssm[8];
    if ((tid & 31) == 0) smx[tid >> 5] = mx;
    __syncthreads();
    mx = smx[0];
#pragma unroll
    for (int i = 1; i < 8; i++) mx = fmaxf(mx, smx[i]);
    float e0 = expf(v0 - mx), e1 = expf(v1 - mx), e2 = expf(v2 - mx), e3 = expf(v3 - mx);
    float s = e0 + e1 + e2 + e3;
#pragma unroll
    for (int o = 16; o > 0; o >>= 1) s += __shfl_xor_sync(0xffffffffu, s, o);
    if ((tid & 31) == 0) ssm[tid >> 5] = s;
    __syncthreads();
    s = ssm[0] + ssm[1] + ssm[2] + ssm[3] + ssm[4] + ssm[5] + ssm[6] + ssm[7];
    float inv = 1.f / s;
    uint4 o4;
    o4.x = packbf(e0 * inv); o4.y = packbf(e1 * inv);
    o4.z = packbf(e2 * inv); o4.w = packbf(e3 * inv);
    *(uint4*)(p + tid * 4) = o4;
}

// ============================================================
// Grid sample, BN fold, c3
// ============================================================
__device__ __forceinline__ int map_idx(int o, int size, bool* valid) {
    float vv = -49.f + 2.f * (float)o;
    float gg = (vv + 51.2f) / 102.4f * 2.f - 1.f;
    float f = ((gg + 1.f) * (float)size - 1.f) * 0.5f;
    int ii = (int)rintf(f);
    *valid = (ii >= 0) && (ii < size);
    return min(max(ii, 0), size - 1);
}

__global__ void k_gridsample() {
    int idx = blockIdx.x * 256 + threadIdx.x;
    if (idx >= 512 * 2500) return;
    int c = idx / 2500, p = idx - c * 2500;
    int oy = p / 50, ox = p - oy * 50;
    bool vy, vx;
    int iy = map_idx(oy, 32, &vy);
    int ix = map_idx(ox, 32, &vx);
    float v = (vy && vx) ? g_x[(size_t)c * 1024 + iy * 32 + ix] : 0.f;
    g_xs[idx] = packbf(v);
}

__global__ void k_bnprep(const float* g1, const float* b1, const float* m1, const float* v1,
                         const float* g2, const float* b2, const float* m2, const float* v2) {
    int c = blockIdx.x * 256 + threadIdx.x;
    if (c >= 512) return;
    float s1 = g1[c] / sqrtf(v1[c] + 1e-5f);
    g_bn[c] = s1;
    g_bn[512 + c] = b1[c] - m1[c] * s1;
    float s2 = g2[c] / sqrtf(v2[c] + 1e-5f);
    g_bn[1024 + c] = s2;
    g_bn[1536 + c] = b2[c] - m2[c] * s2;
}

__global__ void k_c3(const float* __restrict__ w, const float* __restrict__ b,
                     float* __restrict__ out) {
    int idx = blockIdx.x * 256 + threadIdx.x;
    if (idx >= 60000) return;
    int cls = idx / 10000, p = idx - cls * 10000;
    const float* wr = w + cls * 512;
    float s = b[cls];
#pragma unroll 4
    for (int c = 0; c < 512; c++) s += unpackbf(g_y1[(size_t)c * 10000 + p]) * wr[c];
    out[idx] = 1.f / (1.f + expf(-s));
}

// ============================================================
// Host orchestration
// ============================================================
extern "C" void kernel_launch(void* const* d_in, const int* in_sizes, int n_in,
                              void* d_out, int out_size) {
    const float* x       = (const float*)d_in[0];
    const float* qkv_w   = (const float*)d_in[1];
    const float* proj_w  = (const float*)d_in[2];
    const float* proj_b  = (const float*)d_in[3];
    const float* head_w  = (const float*)d_in[4];
    const float* head_b  = (const float*)d_in[5];
    const float* body_w  = (const float*)d_in[6];
    const float* body_b  = (const float*)d_in[7];
    const float* btail_w = (const float*)d_in[8];
    const float* btail_b = (const float*)d_in[9];
    const float* up_w    = (const float*)d_in[10];
    const float* up_b    = (const float*)d_in[11];
    const float* tail_w  = (const float*)d_in[12];
    const float* tail_b  = (const float*)d_in[13];
    const float* c1_w    = (const float*)d_in[14];
    const float* bn1_g   = (const float*)d_in[15];
    const float* bn1_b   = (const float*)d_in[16];
    const float* bn1_m   = (const float*)d_in[17];
    const float* bn1_v   = (const float*)d_in[18];
    const float* c2_w    = (const float*)d_in[19];
    const float* bn2_g   = (const float*)d_in[20];
    const float* bn2_b   = (const float*)d_in[21];
    const float* bn2_m   = (const float*)d_in[22];
    const float* bn2_v   = (const float*)d_in[23];
    const float* c3_w    = (const float*)d_in[24];
    const float* c3_b    = (const float*)d_in[25];
    float* out = (float*)d_out;

    float *p_x, *p_t, *p_qkv, *p_res, *p_bn;
    uint32_t *p_attn, *p_xs, *p_h, *p_r, *p_tmp, *p_u, *p_y1, *p_y2, *p_v, *p_m;
    __nv_bfloat16 *p_uhi, *p_ulo, *p_aqh, *p_aql, *p_aph, *p_apl;
    cudaGetSymbolAddress((void**)&p_x, g_x);
    cudaGetSymbolAddress((void**)&p_t, g_t);
    cudaGetSymbolAddress((void**)&p_qkv, g_qkv);
    cudaGetSymbolAddress((void**)&p_attn, g_attn);
    cudaGetSymbolAddress((void**)&p_res, g_res);
    cudaGetSymbolAddress((void**)&p_xs, g_xs);
    cudaGetSymbolAddress((void**)&p_h, g_h);
    cudaGetSymbolAddress((void**)&p_r, g_r);
    cudaGetSymbolAddress((void**)&p_tmp, g_tmp);
    cudaGetSymbolAddress((void**)&p_u, g_u);
    cudaGetSymbolAddress((void**)&p_y1, g_y1);
    cudaGetSymbolAddress((void**)&p_y2, g_y2);
    cudaGetSymbolAddress((void**)&p_bn, g_bn);
    cudaGetSymbolAddress((void**)&p_v, g_v);
    cudaGetSymbolAddress((void**)&p_m, g_m);
    cudaGetSymbolAddress((void**)&p_uhi, g_uhi);
    cudaGetSymbolAddress((void**)&p_ulo, g_ulo);
    cudaGetSymbolAddress((void**)&p_aqh, g_aqh);
    cudaGetSymbolAddress((void**)&p_aql, g_aql);
    cudaGetSymbolAddress((void**)&p_aph, g_aph);
    cudaGetSymbolAddress((void**)&p_apl, g_apl);

    cudaFuncSetAttribute(k_wgemm, cudaFuncAttributeMaxDynamicSharedMemorySize, SMEM_DYN);
    cudaFuncSetAttribute(k_agemm<0, 2>, cudaFuncAttributeMaxDynamicSharedMemorySize, SMEM_DYN);
    cudaFuncSetAttribute(k_agemm<1, 3>, cudaFuncAttributeMaxDynamicSharedMemorySize, SMEM_DYN);
    cudaFuncSetAttribute(k_agemm<3, 1>, cudaFuncAttributeMaxDynamicSharedMemorySize, SMEM_DYN);
    cudaFuncSetAttribute(k_agemm<0, 0>, cudaFuncAttributeMaxDynamicSharedMemorySize, SMEM_DYN);

    cudaMemcpyAsync(p_x, x, (size_t)512 * 1024 * sizeof(float),
                    cudaMemcpyDeviceToDevice, 0);

    // ---- weight prep ----
    auto wprep1 = [&](const float* w, size_t uoff, int Cout) {
        k_wwino<<<(Cout * 512 + 255) / 256, 256>>>(w, p_uhi + uoff, p_ulo + uoff, Cout, 512);
    };
    wprep1(head_w, U_HEAD, 512);
    k_wtq<<<(8 * 1536 * 512 + 255) / 256, 256>>>(qkv_w, p_aqh, p_aql);
    k_wtp<<<(8 * 512 * 512 + 255) / 256, 256>>>(proj_w, p_aph, p_apl);
    k_wwinoN<<<(16 * 512 * 512 + 255) / 256, 256>>>(body_w, p_uhi + U_BODY(0),
                                                    p_ulo + U_BODY(0), 16);
    wprep1(btail_w, U_BTAIL, 512);
    wprep1(tail_w, U_TAIL, 512);
    wprep1(c1_w, U_C1, 512);
    wprep1(c2_w, U_C2, 512);
    k_wwino<<<(2048 * 512 + 255) / 256, 256>>>(up_w, p_uhi + U_UP, p_ulo + U_UP, 2048, 512);

    const float scale = 0.044194173824159216f;  // 512^-0.5

    // ---- 8 self-attention blocks ----
    for (int i = 0; i < 8; i++) {
        // fused QKV: M=1536; rows<1024 -> g_qkv (feature-major), rows>=1024 -> g_t (token-major)
        k_agemm<0, 2><<<dim3(16, 12, 1), 256, SMEM_DYN>>>(
            p_aqh + (size_t)i * 1536 * 512, p_aql + (size_t)i * 1536 * 512,
            nullptr, p_x, p_qkv, p_t, nullptr, nullptr,
            0, 0, 0, 512, 512, 1024, 1024, 1024, 1.f);
        // scores -> packed S
        k_agemm<1, 3><<<dim3(16, 8, 8), 256, SMEM_DYN>>>(
            nullptr, nullptr, p_qkv, p_qkv + (size_t)512 * 1024, (float*)p_attn, nullptr,
            nullptr, nullptr,
            64 * 1024, 64 * 1024, 1l << 20, 64, 1024, 1024, 1024, 1024, scale);
        k_softmax<<<8192, 256>>>();
        // AV: packed S as A
        k_agemm<3, 1><<<dim3(1, 8, 8), 256, SMEM_DYN>>>(
            nullptr, nullptr, (const float*)p_attn, p_t, p_res, nullptr, nullptr, nullptr,
            1l << 20, 64, 64 * 1024, 1024, 1024, 512, 1024, 64, 1.f);
        // proj + residual
        k_agemm<0, 0><<<dim3(16, 4, 1), 256, SMEM_DYN>>>(
            p_aph + (size_t)i * 512 * 512, p_apl + (size_t)i * 512 * 512,
            nullptr, p_res, p_x, nullptr, proj_b + (size_t)i * 512, p_x,
            0, 0, 0, 512, 512, 1024, 1024, 1024, 1.f);
    }

    // ---- grid transform + BN fold ----
    k_gridsample<<<(512 * 2500 + 255) / 256, 256>>>();
    k_bnprep<<<2, 256>>>(bn1_g, bn1_b, bn1_m, bn1_v, bn2_g, bn2_b, bn2_m, bn2_v);

    // ---- Winograd conv layer ----
    auto wlayer = [&](const uint32_t* in, size_t uoff, const float* bias,
                      const float* bnsc, const float* bnsh, const uint32_t* resid,
                      uint32_t* o, int T, int Cout, int relu, int ps) {
        int H = 2 * T;
        int NTpad = (T * T + 63) / 64 * 64;
        k_wino_in<<<(512 * NTpad + 255) / 256, 256>>>(in, p_v, H, T, NTpad);
        k_wgemm<<<dim3(NTpad / 64, Cout / 128, 16), 256, SMEM_DYN>>>(
            p_uhi + uoff, p_ulo + uoff, p_v, p_m,
            (long)Cout * 512, (long)512 * NTpad, (long)Cout * NTpad, NTpad);
        k_wino_out<<<(Cout * T * T + 255) / 256, 256>>>(
            p_m, o, bias, bnsc, bnsh, resid, Cout, T, NTpad, relu, ps);
    };

    // ---- EDSR upsampler (Winograd) ----
    wlayer(p_xs, U_HEAD, head_b, nullptr, nullptr, nullptr, p_h, 25, 512, 0, 0);
    cudaMemcpyAsync(p_r, p_h, (size_t)512 * 2500 * sizeof(uint32_t),
                    cudaMemcpyDeviceToDevice, 0);
    for (int i = 0; i < 8; i++) {
        wlayer(p_r, U_BODY(2 * i), body_b + (size_t)(2 * i) * 512,
               nullptr, nullptr, nullptr, p_tmp, 25, 512, 1, 0);
        wlayer(p_tmp, U_BODY(2 * i + 1), body_b + (size_t)(2 * i + 1) * 512,
               nullptr, nullptr, p_r, p_r, 25, 512, 0, 0);
    }
    wlayer(p_r, U_BTAIL, btail_b, nullptr, nullptr, p_h, p_tmp, 25, 512, 0, 0);
    wlayer(p_tmp, U_UP, up_b, nullptr, nullptr, nullptr, p_u, 25, 2048, 0, 1);
    wlayer(p_u, U_TAIL, tail_b, nullptr, nullptr, nullptr, p_y1, 50, 512, 0, 0);

    // ---- classifier ----
    wlayer(p_y1, U_C1, nullptr, p_bn, p_bn + 512, nullptr, p_y2, 50, 512, 1, 0);
    wlayer(p_y2, U_C2, nullptr, p_bn + 1024, p_bn + 1536, nullptr, p_y1, 50, 512, 1, 0);
    k_c3<<<(60000 + 255) / 256, 256>>>(c3_w, c3_b, out);
}

// round 17
// speedup vs baseline: 1.7859x; 1.2083x over previous
#include <cuda_runtime.h>
#include <cuda_bf16.h>
#include <math.h>
#include <stdint.h>

// ============================================================
// Static device scratch
// ============================================================
__device__ float g_x[512 * 1024];
__device__ float g_t[1024 * 512];          // V token-major
__device__ float g_qkv[1024 * 1024];       // Q,K feature-major
__device__ uint32_t g_attn[8 * 1024 * 1024]; // packed bf16x2 S
__device__ float g_res[512 * 1024];
__device__ uint32_t g_xs[512 * 2500];
__device__ uint32_t g_h[512 * 2500];
__device__ uint32_t g_r[512 * 2500];
__device__ uint32_t g_tmp[512 * 2500];
__device__ uint32_t g_u[512 * 10000];
__device__ uint32_t g_y1[512 * 10000];
__device__ uint32_t g_y2[512 * 10000];
__device__ float g_bn[2048];

// F(4x4,3x3): 36 points per layer. UL = 36*512*512.
#define UL 9437184
#define U_HEAD  ((size_t)0)
#define U_BODY(i) ((size_t)(1 + (i)) * UL)
#define U_BTAIL ((size_t)17 * UL)
#define U_TAIL  ((size_t)18 * UL)
#define U_C1    ((size_t)19 * UL)
#define U_C2    ((size_t)20 * UL)
#define U_UP    ((size_t)21 * UL)
#define U_TOTAL ((size_t)21 * UL + (size_t)36 * 2048 * 512)
__device__ __nv_bfloat16 g_uhi[U_TOTAL];
__device__ __nv_bfloat16 g_ulo[U_TOTAL];

// V[36][512][NTpad<=640], M[36][Cout<=2048][NTpad]
__device__ uint32_t g_v[36 * 512 * 640];
__device__ uint32_t g_m[36 * 2048 * 192 > 36 * 512 * 640 ? 36 * 2048 * 192 : 36 * 512 * 640];

__device__ __nv_bfloat16 g_aqh[8 * 1536 * 512];
__device__ __nv_bfloat16 g_aql[8 * 1536 * 512];
__device__ __nv_bfloat16 g_aph[8 * 512 * 512];
__device__ __nv_bfloat16 g_apl[8 * 512 * 512];

// ============================================================
// Helpers
// ============================================================
__device__ __forceinline__ uint32_t smem_u32(const void* p) {
    uint32_t a;
    asm("{ .reg .u64 t; cvta.to.shared.u64 t, %1; cvt.u32.u64 %0, t; }"
        : "=r"(a) : "l"(p));
    return a;
}

__device__ __forceinline__ void cpasync16(uint32_t dst, const void* src) {
    asm volatile("cp.async.ca.shared.global [%0], [%1], 16;" :: "r"(dst), "l"(src));
}
#define CP_COMMIT asm volatile("cp.async.commit_group;" ::: "memory")
#define CP_WAIT0  asm volatile("cp.async.wait_group 0;" ::: "memory")

__device__ __forceinline__ void ldsm4(uint32_t addr, uint32_t* r) {
    asm volatile("ldmatrix.sync.aligned.m8n8.x4.shared.b16 {%0,%1,%2,%3}, [%4];"
                 : "=r"(r[0]), "=r"(r[1]), "=r"(r[2]), "=r"(r[3]) : "r"(addr));
}

__device__ __forceinline__ void mma16816(float* d, const uint32_t* a,
                                         uint32_t b0, uint32_t b1) {
    asm volatile(
        "mma.sync.aligned.m16n8k16.row.col.f32.bf16.bf16.f32 "
        "{%0,%1,%2,%3}, {%4,%5,%6,%7}, {%8,%9}, {%0,%1,%2,%3};"
        : "+f"(d[0]), "+f"(d[1]), "+f"(d[2]), "+f"(d[3])
        : "r"(a[0]), "r"(a[1]), "r"(a[2]), "r"(a[3]), "r"(b0), "r"(b1));
}

__device__ __forceinline__ void split2(float v0, float v1, uint32_t& hp, uint32_t& lp) {
    __nv_bfloat16 h0 = __float2bfloat16(v0), h1 = __float2bfloat16(v1);
    __nv_bfloat16 l0 = __float2bfloat16(v0 - __bfloat162float(h0));
    __nv_bfloat16 l1 = __float2bfloat16(v1 - __bfloat162float(h1));
    hp = (uint32_t)__bfloat16_as_ushort(h0) | ((uint32_t)__bfloat16_as_ushort(h1) << 16);
    lp = (uint32_t)__bfloat16_as_ushort(l0) | ((uint32_t)__bfloat16_as_ushort(l1) << 16);
}

__device__ __forceinline__ uint32_t packbf(float v) {
    __nv_bfloat16 h = __float2bfloat16(v);
    __nv_bfloat16 l = __float2bfloat16(v - __bfloat162float(h));
    return (uint32_t)__bfloat16_as_ushort(h) | ((uint32_t)__bfloat16_as_ushort(l) << 16);
}

__device__ __forceinline__ float unpackbf(uint32_t p) {
    return __bfloat162float(__ushort_as_bfloat16((unsigned short)(p & 0xffff))) +
           __bfloat162float(__ushort_as_bfloat16((unsigned short)(p >> 16)));
}

// ============================================================
// Weight prep: F(4x4) Winograd, U = G g G^T (6x6), split hi/lo.
// G = [[1/4,0,0],[-1/6,-1/6,-1/6],[-1/6,1/6,-1/6],
//      [1/24,1/12,1/6],[1/24,-1/12,1/6],[0,0,1]]
// ============================================================
__device__ __forceinline__ void wino_split_one(const float* gp, __nv_bfloat16* uhi,
                                               __nv_bfloat16* ulo, size_t base,
                                               size_t pstride) {
    const float S6 = 1.f / 6.f, S24 = 1.f / 24.f;
    float g[3][3];
#pragma unroll
    for (int i = 0; i < 3; i++)
#pragma unroll
        for (int j = 0; j < 3; j++) g[i][j] = gp[i * 3 + j];
    float t[6][3];
#pragma unroll
    for (int c = 0; c < 3; c++) {
        float a = g[0][c], b = g[1][c], d = g[2][c];
        t[0][c] = 0.25f * a;
        t[1][c] = -(a + b + d) * S6;
        t[2][c] = (-a + b - d) * S6;
        t[3][c] = (a + 2.f * b + 4.f * d) * S24;
        t[4][c] = (a - 2.f * b + 4.f * d) * S24;
        t[5][c] = d;
    }
#pragma unroll
    for (int i = 0; i < 6; i++) {
        float a = t[i][0], b = t[i][1], d = t[i][2];
        float u[6];
        u[0] = 0.25f * a;
        u[1] = -(a + b + d) * S6;
        u[2] = (-a + b - d) * S6;
        u[3] = (a + 2.f * b + 4.f * d) * S24;
        u[4] = (a - 2.f * b + 4.f * d) * S24;
        u[5] = d;
#pragma unroll
        for (int j = 0; j < 6; j++) {
            size_t o = base + (size_t)(i * 6 + j) * pstride;
            float v = u[j];
            __nv_bfloat16 h = __float2bfloat16(v);
            uhi[o] = h;
            ulo[o] = __float2bfloat16(v - __bfloat162float(h));
        }
    }
}

__global__ void k_wwino(const float* __restrict__ w, __nv_bfloat16* __restrict__ uhi,
                        __nv_bfloat16* __restrict__ ulo, int Cout, int Cin) {
    int idx = blockIdx.x * 256 + threadIdx.x;
    if (idx >= Cout * Cin) return;
    wino_split_one(w + (size_t)idx * 9, uhi, ulo, (size_t)idx, (size_t)Cout * Cin);
}

__global__ void k_wwinoN(const float* __restrict__ w, __nv_bfloat16* __restrict__ uhi,
                         __nv_bfloat16* __restrict__ ulo, int nl) {
    int idx = blockIdx.x * 256 + threadIdx.x;
    if (idx >= nl * 512 * 512) return;
    int layer = idx / (512 * 512), r = idx - layer * (512 * 512);
    wino_split_one(w + (size_t)idx * 9, uhi, ulo,
                   (size_t)layer * UL + (size_t)r, (size_t)512 * 512);
}

__global__ void k_wtq(const float* __restrict__ src, __nv_bfloat16* __restrict__ hi,
                      __nv_bfloat16* __restrict__ lo) {
    int idx = blockIdx.x * 256 + threadIdx.x;
    if (idx >= 8 * 1536 * 512) return;
    int blk = idx / (1536 * 512), r = idx - blk * (1536 * 512);
    int f = r >> 9, c = r & 511;
    float v = src[(size_t)blk * 512 * 1536 + c * 1536 + f];
    __nv_bfloat16 h = __float2bfloat16(v);
    hi[idx] = h;
    lo[idx] = __float2bfloat16(v - __bfloat162float(h));
}

__global__ void k_wtp(const float* __restrict__ src, __nv_bfloat16* __restrict__ hi,
                      __nv_bfloat16* __restrict__ lo) {
    int idx = blockIdx.x * 256 + threadIdx.x;
    if (idx >= 8 * 512 * 512) return;
    int blk = idx / (512 * 512), r = idx - blk * (512 * 512);
    int f = r >> 9, c = r & 511;
    float v = src[(size_t)blk * 512 * 512 + c * 512 + f];
    __nv_bfloat16 h = __float2bfloat16(v);
    hi[idx] = h;
    lo[idx] = __float2bfloat16(v - __bfloat162float(h));
}

// ============================================================
// F(4x4) input transform: V = B^T d B (6x6), tiles stride 4, pad 1.
// B^T rows: [4,0,-5,0,1,0],[0,-4,-4,1,1,0],[0,4,-4,-1,1,0],
//           [0,-2,-1,2,1,0],[0,2,-1,-2,1,0],[0,4,0,-5,0,1]
// ============================================================
__device__ __forceinline__ void bt6(const float* d, float* e) {
    e[0] = 4.f * d[0] - 5.f * d[2] + d[4];
    e[1] = -4.f * d[1] - 4.f * d[2] + d[3] + d[4];
    e[2] = 4.f * d[1] - 4.f * d[2] - d[3] + d[4];
    e[3] = -2.f * d[1] - d[2] + 2.f * d[3] + d[4];
    e[4] = 2.f * d[1] - d[2] - 2.f * d[3] + d[4];
    e[5] = 4.f * d[1] - 5.f * d[3] + d[5];
}

__global__ void k_wino_in(const uint32_t* __restrict__ in, uint32_t* __restrict__ V,
                          int H, int T, int NTpad) {
    int idx = blockIdx.x * 256 + threadIdx.x;
    if (idx >= 512 * NTpad) return;
    int c = idx / NTpad, t = idx - c * NTpad;
    size_t pstride = (size_t)512 * NTpad;
    if (t >= T * T) {
#pragma unroll
        for (int p = 0; p < 36; p++) V[(size_t)p * pstride + idx] = 0;
        return;
    }
    int ty = t / T, tx = t - ty * T;
    int r0 = 4 * ty - 1, c0 = 4 * tx - 1;
    const uint32_t* ip = in + (size_t)c * H * H;
    float d[6][6];
#pragma unroll
    for (int i = 0; i < 6; i++) {
        int rr = r0 + i;
        bool rv = (unsigned)rr < (unsigned)H;
#pragma unroll
        for (int j = 0; j < 6; j++) {
            int cc = c0 + j;
            d[i][j] = (rv && (unsigned)cc < (unsigned)H) ? unpackbf(ip[rr * H + cc]) : 0.f;
        }
    }
    float e[6][6];
#pragma unroll
    for (int j = 0; j < 6; j++) {
        float col[6], ec[6];
#pragma unroll
        for (int i = 0; i < 6; i++) col[i] = d[i][j];
        bt6(col, ec);
#pragma unroll
        for (int i = 0; i < 6; i++) e[i][j] = ec[i];
    }
#pragma unroll
    for (int i = 0; i < 6; i++) {
        float f[6];
        bt6(e[i], f);
#pragma unroll
        for (int j = 0; j < 6; j++)
            V[(size_t)(i * 6 + j) * pstride + idx] = packbf(f[j]);
    }
}

// ============================================================
// Shared smem layout for GEMMs
// ============================================================
#define PITCH 80
#define OFF_ALO (128 * PITCH)
#define OFF_BHI (2 * 128 * PITCH)
#define OFF_BLO (OFF_BHI + 64 * PITCH)
#define STAGE   (OFF_BLO + 64 * PITCH)   // 30720
#define SMEM_DYN (2 * STAGE)             // 61440

// ============================================================
// Winograd batched GEMM (proven M=128 x N=64 tile), K=512.
// Packed bf16x2 output. z = 36 points.
// ============================================================
__global__ __launch_bounds__(256, 2)
void k_wgemm(const __nv_bfloat16* __restrict__ Ahi, const __nv_bfloat16* __restrict__ Alo,
             const uint32_t* __restrict__ Bp, uint32_t* __restrict__ outg,
             long aoz, long boz, long coz, int ldb) {
    extern __shared__ char sm[];
    int tid = threadIdx.x, wid = tid >> 5, lane = tid & 31;
    int n0 = blockIdx.x * 64, m0 = blockIdx.y * 128, z = blockIdx.z;
    uint32_t sb = smem_u32(sm);

    int arow = tid >> 1, aseg = tid & 1;
    const __nv_bfloat16* whp = Ahi + (size_t)z * aoz + (size_t)(m0 + arow) * 512 + aseg * 16;
    const __nv_bfloat16* wlp = Alo + (size_t)z * aoz + (size_t)(m0 + arow) * 512 + aseg * 16;
    uint32_t a_off = arow * PITCH + aseg * 32;

    int bpix = tid & 63, bkg = tid >> 6;
    const uint32_t* bbase = Bp + (size_t)z * boz + n0 + bpix;
    uint32_t b_off = OFF_BHI + bpix * PITCH + bkg * 16;

    uint32_t rBp[8];

    auto a_issue = [&](int ch, int buf) {
        int kk = ch << 5;
        uint32_t d0 = sb + a_off + buf * STAGE;
        cpasync16(d0, whp + kk);
        cpasync16(d0 + 16, whp + kk + 8);
        cpasync16(d0 + OFF_ALO, wlp + kk);
        cpasync16(d0 + OFF_ALO + 16, wlp + kk + 8);
        CP_COMMIT;
    };
    auto b_load = [&](int ch) {
        int kk = ch << 5;
#pragma unroll
        for (int j = 0; j < 8; j++)
            rBp[j] = bbase[(size_t)(kk + bkg * 8 + j) * ldb];
    };
    auto b_store = [&](int buf) {
        uint32_t bo = buf * STAGE;
#pragma unroll
        for (int j = 0; j < 8; j += 2) {
            uint32_t hp = __byte_perm(rBp[j], rBp[j + 1], 0x5410);
            uint32_t lp = __byte_perm(rBp[j], rBp[j + 1], 0x7632);
            *(uint32_t*)(sm + (b_off - OFF_BHI) + OFF_BHI + bo + j * 2) = hp;
            *(uint32_t*)(sm + (b_off - OFF_BHI) + OFF_BLO + bo + j * 2) = lp;
        }
    };

    int warp_m = wid & 3, warp_n = wid >> 2;
    uint32_t a_ld = sb + (warp_m * 32 + (lane & 15)) * PITCH + (lane >> 4) * 16;
    uint32_t b_ld = sb + OFF_BHI + (warp_n * 32 + (lane & 15)) * PITCH + (lane >> 4) * 16;

    float acc[2][4][4];
#pragma unroll
    for (int i = 0; i < 2; i++)
#pragma unroll
        for (int j = 0; j < 4; j++)
#pragma unroll
            for (int e = 0; e < 4; e++) acc[i][j][e] = 0.f;

    a_issue(0, 0);
    b_load(0);
    b_store(0);
    CP_WAIT0;
    __syncthreads();

    for (int ch = 0; ch < 16; ch++) {
        if (ch < 15) {
            a_issue(ch + 1, (ch + 1) & 1);
            b_load(ch + 1);
        }
        uint32_t bo = (ch & 1) * STAGE;
#pragma unroll
        for (int ks = 0; ks < 2; ks++) {
            uint32_t Ah[2][4], Al[2][4], Bh[2][4], Bl[2][4];
#pragma unroll
            for (int mt = 0; mt < 2; mt++) {
                ldsm4(a_ld + bo + mt * (16 * PITCH) + ks * 32, Ah[mt]);
                ldsm4(a_ld + bo + OFF_ALO + mt * (16 * PITCH) + ks * 32, Al[mt]);
            }
#pragma unroll
            for (int gq = 0; gq < 2; gq++) {
                ldsm4(b_ld + bo + gq * (16 * PITCH) + ks * 32, Bh[gq]);
                ldsm4(b_ld + bo + (OFF_BLO - OFF_BHI) + gq * (16 * PITCH) + ks * 32, Bl[gq]);
            }
#pragma unroll
            for (int mt = 0; mt < 2; mt++)
#pragma unroll
                for (int nt = 0; nt < 4; nt++) {
                    int gq = nt >> 1, idx = nt & 1;
                    uint32_t bh0 = Bh[gq][idx], bh1 = Bh[gq][idx + 2];
                    uint32_t bl0 = Bl[gq][idx], bl1 = Bl[gq][idx + 2];
                    mma16816(acc[mt][nt], Ah[mt], bh0, bh1);
                    mma16816(acc[mt][nt], Ah[mt], bl0, bl1);
                    mma16816(acc[mt][nt], Al[mt], bh0, bh1);
                }
        }
        if (ch < 15) {
            b_store((ch + 1) & 1);
            CP_WAIT0;
            __syncthreads();
        }
    }

    uint32_t* op = outg + (size_t)z * coz;
#pragma unroll
    for (int mt = 0; mt < 2; mt++) {
#pragma unroll
        for (int half = 0; half < 2; half++) {
            int co = m0 + warp_m * 32 + mt * 16 + (lane >> 2) + half * 8;
#pragma unroll
            for (int nt = 0; nt < 4; nt++) {
#pragma unroll
                for (int e = 0; e < 2; e++) {
                    int p = n0 + warp_n * 32 + nt * 8 + (lane & 3) * 2 + e;
                    op[(size_t)co * ldb + p] = packbf(acc[mt][nt][half * 2 + e]);
                }
            }
        }
    }
}

// ============================================================
// F(4x4) output transform: Y = A^T M A (6x6 -> 4x4), fused epilogue.
// A^T = [[1,1,1,1,1,0],[0,1,-1,2,-2,0],[0,1,1,4,4,0],[0,1,-1,8,-8,1]]
// ============================================================
__device__ __forceinline__ void at6(const float* m, float* s) {
    s[0] = m[0] + m[1] + m[2] + m[3] + m[4];
    s[1] = m[1] - m[2] + 2.f * m[3] - 2.f * m[4];
    s[2] = m[1] + m[2] + 4.f * m[3] + 4.f * m[4];
    s[3] = m[1] - m[2] + 8.f * m[3] - 8.f * m[4] + m[5];
}

__global__ void k_wino_out(const uint32_t* __restrict__ Mb, uint32_t* __restrict__ out,
                           const float* __restrict__ bias,
                           const float* __restrict__ bnsc, const float* __restrict__ bnsh,
                           const uint32_t* __restrict__ resid,
                           int Cout, int H, int T, int NTpad, int relu, int ps) {
    int idx = blockIdx.x * 256 + threadIdx.x;
    if (idx >= Cout * T * T) return;
    int co = idx / (T * T), t = idx - co * (T * T);
    int ty = t / T, tx = t - ty * T;
    int P = H * H;
    size_t pstride = (size_t)Cout * NTpad;
    const uint32_t* mp = Mb + (size_t)co * NTpad + t;
    float m[6][6];
#pragma unroll
    for (int i = 0; i < 6; i++)
#pragma unroll
        for (int j = 0; j < 6; j++)
            m[i][j] = unpackbf(mp[(size_t)(i * 6 + j) * pstride]);
    float s[4][6];
#pragma unroll
    for (int j = 0; j < 6; j++) {
        float col[6], sc[4];
#pragma unroll
        for (int i = 0; i < 6; i++) col[i] = m[i][j];
        at6(col, sc);
#pragma unroll
        for (int i = 0; i < 4; i++) s[i][j] = sc[i];
    }
    float y[4][4];
#pragma unroll
    for (int i = 0; i < 4; i++) at6(s[i], y[i]);

    float bv = bias ? bias[co] : 0.f;
    float sc = bnsc ? bnsc[co] : 1.f;
    float sh = bnsh ? bnsh[co] : 0.f;
#pragma unroll
    for (int i = 0; i < 4; i++) {
        int yy = 4 * ty + i;
        if (yy >= H) continue;
#pragma unroll
        for (int j = 0; j < 4; j++) {
            int xx = 4 * tx + j;
            if (xx >= H) continue;
            int pix = yy * H + xx;
            float v = y[i][j] + bv;
            if (bnsc) v = v * sc + sh;
            if (resid) v += unpackbf(resid[(size_t)co * P + pix]);
            if (relu) v = fmaxf(v, 0.f);
            uint32_t pk = packbf(v);
            if (ps) {
                int c = co >> 2, ry = (co >> 1) & 1, rx = co & 1;
                out[(size_t)c * (4 * P) + (size_t)(2 * yy + ry) * (2 * H) + 2 * xx + rx] = pk;
            } else {
                out[(size_t)co * P + pix] = pk;
            }
        }
    }
}

// ============================================================
// Attention tensor GEMM (unchanged from R14)
// AM: 0 presplit bf16 [m][k]; 1 fp32 [k][m]; 3 packed u32 [m][k]
// TRANS: 0 fp32 [m][n]; 1 fp32 [n][m]; 2 QKV route; 3 packed u32 [m][n]
// ============================================================
template <int AM, int TRANS>
__global__ __launch_bounds__(256, 2)
void k_agemm(const __nv_bfloat16* __restrict__ Ahi, const __nv_bfloat16* __restrict__ Alo,
             const float* __restrict__ Af, const float* __restrict__ Bfg,
             float* __restrict__ outg, float* __restrict__ out2g,
             const float* __restrict__ bias, const float* __restrict__ resid,
             long aoz, long boz, long coz,
             int K, int lda, int ldb, int ldo, int Nn, float scale) {
    extern __shared__ char sm[];
    int tid = threadIdx.x, wid = tid >> 5, lane = tid & 31;
    int n0 = blockIdx.x * 64, m0 = blockIdx.y * 128, z = blockIdx.z;
    uint32_t sb = smem_u32(sm);
    int NCH = K >> 5;

    const float* Bf = Bfg + (size_t)z * boz;
    float* outp = outg + (size_t)z * coz;

    int arow = tid >> 1, aseg = tid & 1;
    int krow = tid >> 3, mseg = tid & 7;
    const __nv_bfloat16 *whp = nullptr, *wlp = nullptr;
    const float* afp = nullptr;
    const uint32_t* app = nullptr;
    if constexpr (AM == 0) {
        whp = Ahi + (size_t)z * aoz + (size_t)(m0 + arow) * lda + aseg * 16;
        wlp = Alo + (size_t)z * aoz + (size_t)(m0 + arow) * lda + aseg * 16;
    } else if constexpr (AM == 1) {
        afp = Af + (size_t)z * aoz + (size_t)krow * lda + m0 + mseg * 16;
    } else {
        app = (const uint32_t*)Af + (size_t)z * aoz + (size_t)(m0 + arow) * lda + aseg * 16;
    }
    uint32_t a_off = arow * PITCH + aseg * 32;

    int bpix = tid & 63, bkg = tid >> 6;
    uint32_t b_off = OFF_BHI + bpix * PITCH + bkg * 16;

    uint4 rAh[2], rAl[2];
    float rA[16];
    uint4 rAp[4];
    float rB[8];

    auto load_gmem = [&](int ch) {
        int kk = ch << 5;
        if constexpr (AM == 0) {
            rAh[0] = *(const uint4*)(whp + kk);
            rAh[1] = *(const uint4*)(whp + kk + 8);
            rAl[0] = *(const uint4*)(wlp + kk);
            rAl[1] = *(const uint4*)(wlp + kk + 8);
        } else if constexpr (AM == 1) {
            const float* p = afp + (size_t)kk * lda;
            *(float4*)(rA + 0) = *(const float4*)(p + 0);
            *(float4*)(rA + 4) = *(const float4*)(p + 4);
            *(float4*)(rA + 8) = *(const float4*)(p + 8);
            *(float4*)(rA + 12) = *(const float4*)(p + 12);
        } else {
            const uint4* p = (const uint4*)(app + kk);
            rAp[0] = p[0]; rAp[1] = p[1]; rAp[2] = p[2]; rAp[3] = p[3];
        }
#pragma unroll
        for (int j = 0; j < 8; j++)
            rB[j] = Bf[(size_t)(kk + bkg * 8 + j) * ldb + n0 + bpix];
    };

    auto store_smem = [&](int buf) {
        uint32_t bo = buf * STAGE;
        if constexpr (AM == 0) {
            *(uint4*)(sm + a_off + bo) = rAh[0];
            *(uint4*)(sm + a_off + bo + 16) = rAh[1];
            *(uint4*)(sm + a_off + bo + OFF_ALO) = rAl[0];
            *(uint4*)(sm + a_off + bo + OFF_ALO + 16) = rAl[1];
        } else if constexpr (AM == 1) {
#pragma unroll
            for (int j = 0; j < 16; j++) {
                float v = rA[j];
                __nv_bfloat16 h = __float2bfloat16(v);
                __nv_bfloat16 l = __float2bfloat16(v - __bfloat162float(h));
                uint32_t off = (mseg * 16 + j) * PITCH + krow * 2;
                *(__nv_bfloat16*)(sm + bo + off) = h;
                *(__nv_bfloat16*)(sm + bo + OFF_ALO + off) = l;
            }
        } else {
            const uint32_t* w = (const uint32_t*)rAp;
            uint32_t hp[8], lp[8];
#pragma unroll
            for (int j = 0; j < 8; j++) {
                hp[j] = __byte_perm(w[2 * j], w[2 * j + 1], 0x5410);
                lp[j] = __byte_perm(w[2 * j], w[2 * j + 1], 0x7632);
            }
            *(uint4*)(sm + bo + a_off) = *(uint4*)hp;
            *(uint4*)(sm + bo + a_off + 16) = *(uint4*)(hp + 4);
            *(uint4*)(sm + bo + OFF_ALO + a_off) = *(uint4*)lp;
            *(uint4*)(sm + bo + OFF_ALO + a_off + 16) = *(uint4*)(lp + 4);
        }
#pragma unroll
        for (int j = 0; j < 8; j += 2) {
            uint32_t hp, lp;
            split2(rB[j], rB[j + 1], hp, lp);
            *(uint32_t*)(sm + (b_off - OFF_BHI) + OFF_BHI + bo + j * 2) = hp;
            *(uint32_t*)(sm + (b_off - OFF_BHI) + OFF_BLO + bo + j * 2) = lp;
        }
    };

    int warp_m = wid & 3, warp_n = wid >> 2;
    uint32_t a_ld = sb + (warp_m * 32 + (lane & 15)) * PITCH + (lane >> 4) * 16;
    uint32_t b_ld = sb + OFF_BHI + (warp_n * 32 + (lane & 15)) * PITCH + (lane >> 4) * 16;

    float acc[2][4][4];
#pragma unroll
    for (int i = 0; i < 2; i++)
#pragma unroll
        for (int j = 0; j < 4; j++)
#pragma unroll
            for (int e = 0; e < 4; e++) acc[i][j][e] = 0.f;

    load_gmem(0);
    store_smem(0);
    __syncthreads();

    for (int ch = 0; ch < NCH; ch++) {
        if (ch + 1 < NCH) load_gmem(ch + 1);
        uint32_t bo = (ch & 1) * STAGE;
#pragma unroll
        for (int ks = 0; ks < 2; ks++) {
            uint32_t Ah[2][4], Al[2][4], Bh[2][4], Bl[2][4];
#pragma unroll
            for (int mt = 0; mt < 2; mt++) {
                ldsm4(a_ld + bo + mt * (16 * PITCH) + ks * 32, Ah[mt]);
                ldsm4(a_ld + bo + OFF_ALO + mt * (16 * PITCH) + ks * 32, Al[mt]);
            }
#pragma unroll
            for (int gq = 0; gq < 2; gq++) {
                ldsm4(b_ld + bo + gq * (16 * PITCH) + ks * 32, Bh[gq]);
                ldsm4(b_ld + bo + (OFF_BLO - OFF_BHI) + gq * (16 * PITCH) + ks * 32, Bl[gq]);
            }
#pragma unroll
            for (int mt = 0; mt < 2; mt++)
#pragma unroll
                for (int nt = 0; nt < 4; nt++) {
                    int gq = nt >> 1, idx = nt & 1;
                    uint32_t bh0 = Bh[gq][idx], bh1 = Bh[gq][idx + 2];
                    uint32_t bl0 = Bl[gq][idx], bl1 = Bl[gq][idx + 2];
                    mma16816(acc[mt][nt], Ah[mt], bh0, bh1);
                    mma16816(acc[mt][nt], Ah[mt], bl0, bl1);
                    mma16816(acc[mt][nt], Al[mt], bh0, bh1);
                }
        }
        if (ch + 1 < NCH) {
            store_smem((ch + 1) & 1);
            __syncthreads();
        }
    }

#pragma unroll
    for (int mt = 0; mt < 2; mt++) {
#pragma unroll
        for (int half = 0; half < 2; half++) {
            int co = m0 + warp_m * 32 + mt * 16 + (lane >> 2) + half * 8;
            float bv = bias ? bias[co] : 0.f;
#pragma unroll
            for (int nt = 0; nt < 4; nt++) {
#pragma unroll
                for (int e = 0; e < 2; e++) {
                    int p = n0 + warp_n * 32 + nt * 8 + (lane & 3) * 2 + e;
                    if (p >= Nn) continue;
                    float v = acc[mt][nt][half * 2 + e] * scale + bv;
                    if (resid) v += resid[(size_t)co * ldo + p];
                    if constexpr (TRANS == 0) {
                        outp[(size_t)co * ldo + p] = v;
                    } else if constexpr (TRANS == 1) {
                        outp[(size_t)p * ldo + co] = v;
                    } else if constexpr (TRANS == 2) {
                        if (co < 1024) outp[(size_t)co * ldo + p] = v;
                        else out2g[(size_t)p * 512 + (co - 1024)] = v;
                    } else {
                        ((uint32_t*)outp)[(size_t)co * ldo + p] = packbf(v);
                    }
                }
            }
        }
    }
}

// ============================================================
// Softmax on packed bf16x2 rows
// ============================================================
__global__ __launch_bounds__(256)
void k_softmax() {
    uint32_t* p = g_attn + (size_t)blockIdx.x * 1024;
    int tid = threadIdx.x;
    uint4 pk = *(uint4*)(p + tid * 4);
    float v0 = unpackbf(pk.x), v1 = unpackbf(pk.y), v2 = unpackbf(pk.z), v3 = unpackbf(pk.w);
    float mx = fmaxf(fmaxf(v0, v1), fmaxf(v2, v3));
#pragma unroll
    for (int o = 16; o > 0; o >>= 1) mx = fmaxf(mx, __shfl_xor_sync(0xffffffffu, mx, o));
    __shared__ float smx[8], ssm[8];
    if ((tid & 31) == 0) smx[tid >> 5] = mx;
    __syncthreads();
    mx = smx[0];
#pragma unroll
    for (int i = 1; i < 8; i++) mx = fmaxf(mx, smx[i]);
    float e0 = expf(v0 - mx), e1 = expf(v1 - mx), e2 = expf(v2 - mx), e3 = expf(v3 - mx);
    float s = e0 + e1 + e2 + e3;
#pragma unroll
    for (int o = 16; o > 0; o >>= 1) s += __shfl_xor_sync(0xffffffffu, s, o);
    if ((tid & 31) == 0) ssm[tid >> 5] = s;
    __syncthreads();
    s = ssm[0] + ssm[1] + ssm[2] + ssm[3] + ssm[4] + ssm[5] + ssm[6] + ssm[7];
    float inv = 1.f / s;
    uint4 o4;
    o4.x = packbf(e0 * inv); o4.y = packbf(e1 * inv);
    o4.z = packbf(e2 * inv); o4.w = packbf(e3 * inv);
    *(uint4*)(p + tid * 4) = o4;
}

// ============================================================
// Grid sample, BN fold, c3
// ============================================================
__device__ __forceinline__ int map_idx(int o, int size, bool* valid) {
    float vv = -49.f + 2.f * (float)o;
    float gg = (vv + 51.2f) / 102.4f * 2.f - 1.f;
    float f = ((gg + 1.f) * (float)size - 1.f) * 0.5f;
    int ii = (int)rintf(f);
    *valid = (ii >= 0) && (ii < size);
    return min(max(ii, 0), size - 1);
}

__global__ void k_gridsample() {
    int idx = blockIdx.x * 256 + threadIdx.x;
    if (idx >= 512 * 2500) return;
    int c = idx / 2500, p = idx - c * 2500;
    int oy = p / 50, ox = p - oy * 50;
    bool vy, vx;
    int iy = map_idx(oy, 32, &vy);
    int ix = map_idx(ox, 32, &vx);
    float v = (vy && vx) ? g_x[(size_t)c * 1024 + iy * 32 + ix] : 0.f;
    g_xs[idx] = packbf(v);
}

__global__ void k_bnprep(const float* g1, const float* b1, const float* m1, const float* v1,
                         const float* g2, const float* b2, const float* m2, const float* v2) {
    int c = blockIdx.x * 256 + threadIdx.x;
    if (c >= 512) return;
    float s1 = g1[c] / sqrtf(v1[c] + 1e-5f);
    g_bn[c] = s1;
    g_bn[512 + c] = b1[c] - m1[c] * s1;
    float s2 = g2[c] / sqrtf(v2[c] + 1e-5f);
    g_bn[1024 + c] = s2;
    g_bn[1536 + c] = b2[c] - m2[c] * s2;
}

__global__ void k_c3(const float* __restrict__ w, const float* __restrict__ b,
                     float* __restrict__ out) {
    int idx = blockIdx.x * 256 + threadIdx.x;
    if (idx >= 60000) return;
    int cls = idx / 10000, p = idx - cls * 10000;
    const float* wr = w + cls * 512;
    float s = b[cls];
#pragma unroll 4
    for (int c = 0; c < 512; c++) s += unpackbf(g_y1[(size_t)c * 10000 + p]) * wr[c];
    out[idx] = 1.f / (1.f + expf(-s));
}

// ============================================================
// Host orchestration
// ============================================================
extern "C" void kernel_launch(void* const* d_in, const int* in_sizes, int n_in,
                              void* d_out, int out_size) {
    const float* x       = (const float*)d_in[0];
    const float* qkv_w   = (const float*)d_in[1];
    const float* proj_w  = (const float*)d_in[2];
    const float* proj_b  = (const float*)d_in[3];
    const float* head_w  = (const float*)d_in[4];
    const float* head_b  = (const float*)d_in[5];
    const float* body_w  = (const float*)d_in[6];
    const float* body_b  = (const float*)d_in[7];
    const float* btail_w = (const float*)d_in[8];
    const float* btail_b = (const float*)d_in[9];
    const float* up_w    = (const float*)d_in[10];
    const float* up_b    = (const float*)d_in[11];
    const float* tail_w  = (const float*)d_in[12];
    const float* tail_b  = (const float*)d_in[13];
    const float* c1_w    = (const float*)d_in[14];
    const float* bn1_g   = (const float*)d_in[15];
    const float* bn1_b   = (const float*)d_in[16];
    const float* bn1_m   = (const float*)d_in[17];
    const float* bn1_v   = (const float*)d_in[18];
    const float* c2_w    = (const float*)d_in[19];
    const float* bn2_g   = (const float*)d_in[20];
    const float* bn2_b   = (const float*)d_in[21];
    const float* bn2_m   = (const float*)d_in[22];
    const float* bn2_v   = (const float*)d_in[23];
    const float* c3_w    = (const float*)d_in[24];
    const float* c3_b    = (const float*)d_in[25];
    float* out = (float*)d_out;

    float *p_x, *p_t, *p_qkv, *p_res, *p_bn;
    uint32_t *p_attn, *p_xs, *p_h, *p_r, *p_tmp, *p_u, *p_y1, *p_y2, *p_v, *p_m;
    __nv_bfloat16 *p_uhi, *p_ulo, *p_aqh, *p_aql, *p_aph, *p_apl;
    cudaGetSymbolAddress((void**)&p_x, g_x);
    cudaGetSymbolAddress((void**)&p_t, g_t);
    cudaGetSymbolAddress((void**)&p_qkv, g_qkv);
    cudaGetSymbolAddress((void**)&p_attn, g_attn);
    cudaGetSymbolAddress((void**)&p_res, g_res);
    cudaGetSymbolAddress((void**)&p_xs, g_xs);
    cudaGetSymbolAddress((void**)&p_h, g_h);
    cudaGetSymbolAddress((void**)&p_r, g_r);
    cudaGetSymbolAddress((void**)&p_tmp, g_tmp);
    cudaGetSymbolAddress((void**)&p_u, g_u);
    cudaGetSymbolAddress((void**)&p_y1, g_y1);
    cudaGetSymbolAddress((void**)&p_y2, g_y2);
    cudaGetSymbolAddress((void**)&p_bn, g_bn);
    cudaGetSymbolAddress((void**)&p_v, g_v);
    cudaGetSymbolAddress((void**)&p_m, g_m);
    cudaGetSymbolAddress((void**)&p_uhi, g_uhi);
    cudaGetSymbolAddress((void**)&p_ulo, g_ulo);
    cudaGetSymbolAddress((void**)&p_aqh, g_aqh);
    cudaGetSymbolAddress((void**)&p_aql, g_aql);
    cudaGetSymbolAddress((void**)&p_aph, g_aph);
    cudaGetSymbolAddress((void**)&p_apl, g_apl);

    cudaFuncSetAttribute(k_wgemm, cudaFuncAttributeMaxDynamicSharedMemorySize, SMEM_DYN);
    cudaFuncSetAttribute(k_agemm<0, 2>, cudaFuncAttributeMaxDynamicSharedMemorySize, SMEM_DYN);
    cudaFuncSetAttribute(k_agemm<1, 3>, cudaFuncAttributeMaxDynamicSharedMemorySize, SMEM_DYN);
    cudaFuncSetAttribute(k_agemm<3, 1>, cudaFuncAttributeMaxDynamicSharedMemorySize, SMEM_DYN);
    cudaFuncSetAttribute(k_agemm<0, 0>, cudaFuncAttributeMaxDynamicSharedMemorySize, SMEM_DYN);

    cudaMemcpyAsync(p_x, x, (size_t)512 * 1024 * sizeof(float),
                    cudaMemcpyDeviceToDevice, 0);

    // ---- weight prep (F(4x4) transforms) ----
    auto wprep1 = [&](const float* w, size_t uoff, int Cout) {
        k_wwino<<<(Cout * 512 + 255) / 256, 256>>>(w, p_uhi + uoff, p_ulo + uoff, Cout, 512);
    };
    wprep1(head_w, U_HEAD, 512);
    k_wtq<<<(8 * 1536 * 512 + 255) / 256, 256>>>(qkv_w, p_aqh, p_aql);
    k_wtp<<<(8 * 512 * 512 + 255) / 256, 256>>>(proj_w, p_aph, p_apl);
    k_wwinoN<<<(16 * 512 * 512 + 255) / 256, 256>>>(body_w, p_uhi + U_BODY(0),
                                                    p_ulo + U_BODY(0), 16);
    wprep1(btail_w, U_BTAIL, 512);
    wprep1(tail_w, U_TAIL, 512);
    wprep1(c1_w, U_C1, 512);
    wprep1(c2_w, U_C2, 512);
    k_wwino<<<(2048 * 512 + 255) / 256, 256>>>(up_w, p_uhi + U_UP, p_ulo + U_UP, 2048, 512);

    const float scale = 0.044194173824159216f;  // 512^-0.5

    // ---- 8 self-attention blocks ----
    for (int i = 0; i < 8; i++) {
        k_agemm<0, 2><<<dim3(16, 12, 1), 256, SMEM_DYN>>>(
            p_aqh + (size_t)i * 1536 * 512, p_aql + (size_t)i * 1536 * 512,
            nullptr, p_x, p_qkv, p_t, nullptr, nullptr,
            0, 0, 0, 512, 512, 1024, 1024, 1024, 1.f);
        k_agemm<1, 3><<<dim3(16, 8, 8), 256, SMEM_DYN>>>(
            nullptr, nullptr, p_qkv, p_qkv + (size_t)512 * 1024, (float*)p_attn, nullptr,
            nullptr, nullptr,
            64 * 1024, 64 * 1024, 1l << 20, 64, 1024, 1024, 1024, 1024, scale);
        k_softmax<<<8192, 256>>>();
        k_agemm<3, 1><<<dim3(1, 8, 8), 256, SMEM_DYN>>>(
            nullptr, nullptr, (const float*)p_attn, p_t, p_res, nullptr, nullptr, nullptr,
            1l << 20, 64, 64 * 1024, 1024, 1024, 512, 1024, 64, 1.f);
        k_agemm<0, 0><<<dim3(16, 4, 1), 256, SMEM_DYN>>>(
            p_aph + (size_t)i * 512 * 512, p_apl + (size_t)i * 512 * 512,
            nullptr, p_res, p_x, nullptr, proj_b + (size_t)i * 512, p_x,
            0, 0, 0, 512, 512, 1024, 1024, 1024, 1.f);
    }

    // ---- grid transform + BN fold ----
    k_gridsample<<<(512 * 2500 + 255) / 256, 256>>>();
    k_bnprep<<<2, 256>>>(bn1_g, bn1_b, bn1_m, bn1_v, bn2_g, bn2_b, bn2_m, bn2_v);

    // ---- F(4x4) Winograd conv layer ----
    auto wlayer = [&](const uint32_t* in, size_t uoff, const float* bias,
                      const float* bnsc, const float* bnsh, const uint32_t* resid,
                      uint32_t* o, int H, int Cout, int relu, int ps) {
        int T = (H + 3) / 4;
        int NTpad = (T * T + 63) / 64 * 64;
        k_wino_in<<<(512 * NTpad + 255) / 256, 256>>>(in, p_v, H, T, NTpad);
        k_wgemm<<<dim3(NTpad / 64, Cout / 128, 36), 256, SMEM_DYN>>>(
            p_uhi + uoff, p_ulo + uoff, p_v, p_m,
            (long)Cout * 512, (long)512 * NTpad, (long)Cout * NTpad, NTpad);
        k_wino_out<<<(Cout * T * T + 255) / 256, 256>>>(
            p_m, o, bias, bnsc, bnsh, resid, Cout, H, T, NTpad, relu, ps);
    };

    // ---- EDSR upsampler ----
    wlayer(p_xs, U_HEAD, head_b, nullptr, nullptr, nullptr, p_h, 50, 512, 0, 0);
    cudaMemcpyAsync(p_r, p_h, (size_t)512 * 2500 * sizeof(uint32_t),
                    cudaMemcpyDeviceToDevice, 0);
    for (int i = 0; i < 8; i++) {
        wlayer(p_r, U_BODY(2 * i), body_b + (size_t)(2 * i) * 512,
               nullptr, nullptr, nullptr, p_tmp, 50, 512, 1, 0);
        wlayer(p_tmp, U_BODY(2 * i + 1), body_b + (size_t)(2 * i + 1) * 512,
               nullptr, nullptr, p_r, p_r, 50, 512, 0, 0);
    }
    wlayer(p_r, U_BTAIL, btail_b, nullptr, nullptr, p_h, p_tmp, 50, 512, 0, 0);
    wlayer(p_tmp, U_UP, up_b, nullptr, nullptr, nullptr, p_u, 50, 2048, 0, 1);
    wlayer(p_u, U_TAIL, tail_b, nullptr, nullptr, nullptr, p_y1, 100, 512, 0, 0);

    // ---- classifier ----
    wlayer(p_y1, U_C1, nullptr, p_bn, p_bn + 512, nullptr, p_y2, 100, 512, 1, 0);
    wlayer(p_y2, U_C2, nullptr, p_bn + 1024, p_bn + 1536, nullptr, p_y1, 100, 512, 1, 0);
    k_c3<<<(60000 + 255) / 256, 256>>>(c3_w, c3_b, out);
}